// round 5
// baseline (speedup 1.0000x reference)
#include <cuda_runtime.h>
#include <cuda_bf16.h>
#include <cstdint>

#define NNODES 20000
#define NEDGES 160000
#define BBATCH 64
#define FTEXT  300
#define YS     320          // padded K stride for layer-1 GEMM operands
#define FHID   1024
#define FOUT   1664
#define NEG_SLOPE 0.2f
#define NSPLIT 13           // T1 split-K factor (13 * 128 = 1664)

#define G1_GRID (16 * 157)  // GEMM1 CTAs: N/64 x ceil(M/128)
#define AGG_BLKS 10000      // aggY blocks (2 nodes each)

// ---------------- scratch ----------------
__device__ float g_deg[NNODES];
__device__ float g_dinv[NNODES];
__device__ int   g_cnt[NNODES];
__device__ int   g_rowptr[NNODES + 1];
__device__ int   g_cursor[NNODES];
__device__ int   g_colsrc[NEDGES];
__device__ float g_colw[NEDGES];
__device__ __nv_bfloat16 g_Yh[(size_t)NNODES * YS];
__device__ __nv_bfloat16 g_Yl[(size_t)NNODES * YS];
__device__ __nv_bfloat16 g_W1h[(size_t)FHID * YS];
__device__ __nv_bfloat16 g_W1l[(size_t)FHID * YS];
__device__ __nv_bfloat16 g_X1h[(size_t)NNODES * FHID];
__device__ __nv_bfloat16 g_X1l[(size_t)NNODES * FHID];
__device__ float g_T1p[(size_t)NSPLIT * BBATCH * FHID];
__device__ __nv_bfloat16 g_T1h[BBATCH * FHID];
__device__ __nv_bfloat16 g_T1l[BBATCH * FHID];
__device__ float g_T2[(size_t)NNODES * BBATCH];
__device__ float g_imgb2[BBATCH];

// ---------------- PTX helpers (sm_80+ baseline only) ----------------
__device__ __forceinline__ uint32_t smem_to_u32(const void* p) {
    uint32_t a;
    asm("{ .reg .u64 t; cvta.to.shared.u64 t, %1; cvt.u32.u64 %0, t; }" : "=r"(a) : "l"(p));
    return a;
}
__device__ __forceinline__ void ldsm_x4(uint32_t* r, uint32_t addr) {
    asm volatile("ldmatrix.sync.aligned.m8n8.x4.shared.b16 {%0,%1,%2,%3}, [%4];"
        : "=r"(r[0]), "=r"(r[1]), "=r"(r[2]), "=r"(r[3]) : "r"(addr));
}
__device__ __forceinline__ void mma_bf16(float* c, const uint32_t* a, const uint32_t* b) {
    asm volatile(
        "mma.sync.aligned.m16n8k16.row.col.f32.bf16.bf16.f32 "
        "{%0,%1,%2,%3}, {%4,%5,%6,%7}, {%8,%9}, {%0,%1,%2,%3};"
        : "+f"(c[0]), "+f"(c[1]), "+f"(c[2]), "+f"(c[3])
        : "r"(a[0]), "r"(a[1]), "r"(a[2]), "r"(a[3]), "r"(b[0]), "r"(b[1]));
}
__device__ __forceinline__ void cpa16(uint32_t dst, const void* src, uint32_t srcsz) {
    asm volatile("cp.async.ca.shared.global [%0], [%1], 16, %2;"
        :: "r"(dst), "l"(src), "r"(srcsz) : "memory");
}
#define CP_COMMIT() asm volatile("cp.async.commit_group;" ::: "memory")
#define CP_WAIT0()  asm volatile("cp.async.wait_group 0;" ::: "memory")
#define CP_WAIT1()  asm volatile("cp.async.wait_group 1;" ::: "memory")

// ---------------- launch 0: zero scratch + split-transpose W1 ----------------
__global__ void k_init(const float* __restrict__ W1) {
    const int ZBLK = 79;
    int tid = threadIdx.x;
    if (blockIdx.x < ZBLK) {
        int i = blockIdx.x * 256 + tid;
        if (i < NNODES) { g_deg[i] = 0.f; g_cnt[i] = 0; g_cursor[i] = 0; }
    } else {
        __shared__ float s[32][33];
        int bidx = blockIdx.x - ZBLK;          // 0..319
        int n0 = (bidx & 31) * 32;
        int k0 = (bidx >> 5) * 32;             // 0..288
        int tx = tid & 31, ty = tid >> 5;
        #pragma unroll
        for (int i = 0; i < 32; i += 8) {
            int k = k0 + ty + i, n = n0 + tx;
            s[ty + i][tx] = (k < FTEXT) ? W1[(size_t)k * FHID + n] : 0.f;
        }
        __syncthreads();
        #pragma unroll
        for (int i = 0; i < 32; i += 8) {
            int n = n0 + ty + i, k = k0 + tx;
            float v = s[tx][ty + i];
            __nv_bfloat16 h = __float2bfloat16_rn(v);
            __nv_bfloat16 l = __float2bfloat16_rn(v - __bfloat162float(h));
            g_W1h[(size_t)n * YS + k] = h;
            g_W1l[(size_t)n * YS + k] = l;
        }
    }
}

// ---------------- launch 1: degree ----------------
__global__ void k_deg(const int* __restrict__ dst, const float* __restrict__ w) {
    int e = blockIdx.x * blockDim.x + threadIdx.x;
    if (e < NEDGES) {
        int d = dst[e];
        atomicAdd(&g_deg[d], w[e]);
        atomicAdd(&g_cnt[d], 1);
    }
}

// ---------------- launch 2: warp-shuffle scan + dinv ----------------
__global__ void k_scandinv() {
    const int CH = 20;
    __shared__ int wtot[32];
    __shared__ int s_total;
    int t = threadIdx.x;
    int lane = t & 31, wid = t >> 5;
    int base = t * CH;
    int loc[CH];
    int sum = 0;
    #pragma unroll
    for (int i = 0; i < CH; i++) {
        int idx = base + i;
        int v = 0;
        if (idx < NNODES) {
            v = g_cnt[idx];
            float d = g_deg[idx];
            g_dinv[idx] = (d > 0.f) ? rsqrtf(d) : 0.f;
        }
        loc[i] = sum;
        sum += v;
    }
    int inc = sum;
    #pragma unroll
    for (int off = 1; off < 32; off <<= 1) {
        int v = __shfl_up_sync(0xffffffffu, inc, off);
        if (lane >= off) inc += v;
    }
    if (lane == 31) wtot[wid] = inc;
    __syncthreads();
    if (wid == 0) {
        int v = wtot[lane];
        int wi = v;
        #pragma unroll
        for (int off = 1; off < 32; off <<= 1) {
            int u = __shfl_up_sync(0xffffffffu, wi, off);
            if (lane >= off) wi += u;
        }
        wtot[lane] = wi - v;
        if (lane == 31) s_total = wi;
    }
    __syncthreads();
    int off0 = wtot[wid] + inc - sum;
    #pragma unroll
    for (int i = 0; i < CH; i++) {
        int idx = base + i;
        if (idx < NNODES) g_rowptr[idx] = off0 + loc[i];
    }
    if (t == 0) g_rowptr[NNODES] = s_total;
}

// ---------------- launch 3: fill CSR ----------------
__global__ void k_fill(const int* __restrict__ src, const int* __restrict__ dst,
                       const float* __restrict__ w) {
    int e = blockIdx.x * blockDim.x + threadIdx.x;
    if (e < NEDGES) {
        int s = src[e], d = dst[e];
        float nm = g_dinv[s] * w[e] * g_dinv[d];
        int pos = g_rowptr[d] + atomicAdd(&g_cursor[d], 1);
        g_colsrc[pos] = s;
        g_colw[pos]   = nm;
    }
}

// ---------------- launch 4: aggY (split bf16 out) + T1 split-K ----------------
__global__ void __launch_bounds__(256) k_agg_t1(
    const float* __restrict__ X, const float* __restrict__ img,
    const float* __restrict__ W2)
{
    __shared__ int   ss[2][128];
    __shared__ float sw[2][128];
    __shared__ float As[16][64 + 1];
    __shared__ float Bs[16][64 + 1];
    int tid = threadIdx.x;

    if (blockIdx.x < AGG_BLKS) {
        int sub = tid >> 7;             // 0/1: node within block
        int t2 = tid & 127;
        int n = blockIdx.x * 2 + sub;
        int st = g_rowptr[n], en = g_rowptr[n + 1];
        float acc0 = 0.f, acc1 = 0.f, acc2 = 0.f;
        for (int e0 = st; e0 < en; e0 += 128) {
            int ne = min(128, en - e0);
            if (t2 < ne) { ss[sub][t2] = g_colsrc[e0 + t2]; sw[sub][t2] = g_colw[e0 + t2]; }
            __syncwarp();
            asm volatile("bar.sync %0, 128;" :: "r"(sub + 1) : "memory");
            for (int j = 0; j < ne; j++) {
                const float* xr = X + (size_t)ss[sub][j] * FTEXT;
                float wv = sw[sub][j];
                acc0 += wv * xr[t2];
                acc1 += wv * xr[t2 + 128];
                if (t2 + 256 < FTEXT) acc2 += wv * xr[t2 + 256];
            }
            asm volatile("bar.sync %0, 128;" :: "r"(sub + 1) : "memory");
        }
        size_t rb = (size_t)n * YS;
        float v[3] = {acc0, acc1, acc2};
        #pragma unroll
        for (int q = 0; q < 3; q++) {
            int col = t2 + q * 128;
            if (col < FTEXT) {
                __nv_bfloat16 h = __float2bfloat16_rn(v[q]);
                __nv_bfloat16 l = __float2bfloat16_rn(v[q] - __bfloat162float(h));
                g_Yh[rb + col] = h;
                g_Yl[rb + col] = l;
            }
        }
        if (t2 < YS - FTEXT) {          // zero the K pad 300..319
            g_Yh[rb + FTEXT + t2] = __nv_bfloat16(0.f);
            g_Yl[rb + FTEXT + t2] = __nv_bfloat16(0.f);
        }
    } else {
        // T1 partials: part[s][b][n] = sum_{k in s-th 128} img[b,k] * W2[n,k]
        int bidx = blockIdx.x - AGG_BLKS;     // 0..207
        int col0 = (bidx & 15) * 64;
        int s = bidx >> 4;
        int kbase = s * 128;
        const int BK = 16;
        int tx = tid & 15, ty = tid >> 4;
        float acc[4][4] = {};
        int r = tid >> 2, kq = (tid & 3) * 4;
        for (int t0 = 0; t0 < 128; t0 += BK) {
            float4 av = *(const float4*)(img + (size_t)r * FOUT + kbase + t0 + kq);
            As[kq + 0][r] = av.x; As[kq + 1][r] = av.y;
            As[kq + 2][r] = av.z; As[kq + 3][r] = av.w;
            float4 bv = *(const float4*)(W2 + (size_t)(col0 + r) * FOUT + kbase + t0 + kq);
            Bs[kq + 0][r] = bv.x; Bs[kq + 1][r] = bv.y;
            Bs[kq + 2][r] = bv.z; Bs[kq + 3][r] = bv.w;
            __syncthreads();
            #pragma unroll
            for (int k = 0; k < BK; k++) {
                float a[4], b[4];
                #pragma unroll
                for (int i = 0; i < 4; i++) a[i] = As[k][ty * 4 + i];
                #pragma unroll
                for (int j = 0; j < 4; j++) b[j] = Bs[k][tx * 4 + j];
                #pragma unroll
                for (int i = 0; i < 4; i++)
                    #pragma unroll
                    for (int j = 0; j < 4; j++)
                        acc[i][j] += a[i] * b[j];
            }
            __syncthreads();
        }
        float* cp = g_T1p + (size_t)s * (BBATCH * FHID);
        #pragma unroll
        for (int i = 0; i < 4; i++) {
            int b = ty * 4 + i;
            #pragma unroll
            for (int j = 0; j < 4; j++)
                cp[(size_t)b * FHID + col0 + tx * 4 + j] = acc[i][j];
        }
    }
}

// ---------------- bf16x3 GEMM core: pre-split operands + cp.async 3-stage ----
// C[M,N(=64*gridN)] = (Ah+Al)[M,K] @ (Bh+Bl)[N,K]^T,  hh+hl+lh accumulation.
template<bool BIAS, bool LEAKY, bool SPLIT_OUT>
__device__ __forceinline__ void gemm_core(
    const __nv_bfloat16* __restrict__ Ah, const __nv_bfloat16* __restrict__ Al, int lda,
    const __nv_bfloat16* __restrict__ Bh, const __nv_bfloat16* __restrict__ Bl, int ldb,
    float* __restrict__ C, __nv_bfloat16* __restrict__ Ch, __nv_bfloat16* __restrict__ Cl,
    int ldc, const float* __restrict__ bias, int M, int nT, int bx, int by, char* smem)
{
    const int AHOFF = 0, ALOFF = 10240, BHOFF = 20480, BLOFF = 25600;
    const int STAGE = 30720;

    int tid  = threadIdx.x;
    int wid  = tid >> 5, lane = tid & 31;
    int wm   = wid & 3, wn = wid >> 2;
    int row0 = by * 128;
    int col0 = bx * 64;
    uint32_t smem_u = smem_to_u32(smem);

    float acc[2][4][4];
    #pragma unroll
    for (int mt = 0; mt < 2; mt++)
        #pragma unroll
        for (int nt = 0; nt < 4; nt++)
            #pragma unroll
            for (int q = 0; q < 4; q++) acc[mt][nt][q] = 0.f;

    // per-thread copy coordinates
    int ar = tid >> 2, ac = (tid & 3) * 8;           // A: 2 rows per thread (ar, ar+64)
    int br = tid >> 2, bc = (tid & 3) * 8;           // B: 1 row per thread

    auto ISSUE = [&](int t, int buf) {
        int kb = t * 32;
        uint32_t sb = smem_u + buf * STAGE;
        #pragma unroll
        for (int i = 0; i < 2; i++) {
            int r = ar + i * 64;
            int row = row0 + r;
            uint32_t ok = (row < M) ? 16u : 0u;
            int rc = (row < M) ? row : (M - 1);
            uint32_t d = sb + (uint32_t)(r * 80 + ac * 2);
            cpa16(d + AHOFF, Ah + (size_t)rc * lda + kb + ac, ok);
            cpa16(d + ALOFF, Al + (size_t)rc * lda + kb + ac, ok);
        }
        {
            uint32_t d = sb + (uint32_t)(br * 80 + bc * 2);
            cpa16(d + BHOFF, Bh + (size_t)(col0 + br) * ldb + kb + bc, 16u);
            cpa16(d + BLOFF, Bl + (size_t)(col0 + br) * ldb + kb + bc, 16u);
        }
        CP_COMMIT();
    };

    auto COMPUTE = [&](int buf) {
        uint32_t sb = smem_u + buf * STAGE;
        uint32_t aH = sb + AHOFF + (uint32_t)((wm * 32 + (lane & 15)) * 80 + (lane >> 4) * 16);
        uint32_t aL = sb + ALOFF + (uint32_t)((wm * 32 + (lane & 15)) * 80 + (lane >> 4) * 16);
        uint32_t bH = sb + BHOFF +
            (uint32_t)((wn * 32 + ((lane >> 4) & 1) * 8 + (lane & 7)) * 80 + ((lane >> 3) & 1) * 16);
        uint32_t bL = bH + (BLOFF - BHOFF);
        #pragma unroll
        for (int ks = 0; ks < 2; ks++) {
            uint32_t ah[2][4], al[2][4], bh[2][4], bl[2][4];
            #pragma unroll
            for (int mt = 0; mt < 2; mt++) {
                ldsm_x4(ah[mt], aH + mt * 16 * 80 + ks * 32);
                ldsm_x4(al[mt], aL + mt * 16 * 80 + ks * 32);
            }
            #pragma unroll
            for (int g = 0; g < 2; g++) {
                ldsm_x4(bh[g], bH + g * 16 * 80 + ks * 32);
                ldsm_x4(bl[g], bL + g * 16 * 80 + ks * 32);
            }
            #pragma unroll
            for (int mt = 0; mt < 2; mt++)
                #pragma unroll
                for (int nt = 0; nt < 4; nt++) {
                    const uint32_t* ph = &bh[nt >> 1][(nt & 1) * 2];
                    const uint32_t* pl = &bl[nt >> 1][(nt & 1) * 2];
                    mma_bf16(acc[mt][nt], ah[mt], ph);
                    mma_bf16(acc[mt][nt], ah[mt], pl);
                    mma_bf16(acc[mt][nt], al[mt], ph);
                }
        }
    };

    // 3-stage pipeline
    ISSUE(0, 0);
    if (nT > 1) ISSUE(1, 1);
    for (int t = 0; t < nT; t++) {
        if (t == nT - 1) { CP_WAIT0(); } else { CP_WAIT1(); }
        __syncthreads();
        if (t + 2 < nT) ISSUE(t + 2, (t + 2) % 3);
        COMPUTE(t % 3);
        __syncthreads();
    }

    // epilogue
    int rw = row0 + wm * 32;
    int cw = col0 + wn * 32;
    #pragma unroll
    for (int mt = 0; mt < 2; mt++) {
        #pragma unroll
        for (int half = 0; half < 2; half++) {
            int row = rw + mt * 16 + (lane >> 2) + half * 8;
            if (row >= M) continue;
            #pragma unroll
            for (int nt = 0; nt < 4; nt++) {
                int col = cw + nt * 8 + (lane & 3) * 2;
                float v0 = acc[mt][nt][half * 2 + 0];
                float v1 = acc[mt][nt][half * 2 + 1];
                if (BIAS) { v0 += bias[col]; v1 += bias[col + 1]; }
                if (LEAKY) {
                    v0 = (v0 >= 0.f) ? v0 : NEG_SLOPE * v0;
                    v1 = (v1 >= 0.f) ? v1 : NEG_SLOPE * v1;
                }
                if (SPLIT_OUT) {
                    __nv_bfloat16 h0 = __float2bfloat16_rn(v0);
                    __nv_bfloat16 h1 = __float2bfloat16_rn(v1);
                    __nv_bfloat16 l0 = __float2bfloat16_rn(v0 - __bfloat162float(h0));
                    __nv_bfloat16 l1 = __float2bfloat16_rn(v1 - __bfloat162float(h1));
                    __nv_bfloat162 hp(h0, h1), lp(l0, l1);
                    *(uint32_t*)(Ch + (size_t)row * ldc + col) = *(uint32_t*)&hp;
                    *(uint32_t*)(Cl + (size_t)row * ldc + col) = *(uint32_t*)&lp;
                } else {
                    float2 o; o.x = v0; o.y = v1;
                    *(float2*)(C + (size_t)row * ldc + col) = o;
                }
            }
        }
    }
}

// ---------------- launch 5: GEMM1 (X1 split out) + T1 reduce + imgb2 ----------
__global__ void __launch_bounds__(256, 2) k_l5(
    const float* __restrict__ b1, const float* __restrict__ img,
    const float* __restrict__ b2)
{
    extern __shared__ char smem[];
    if (blockIdx.x < G1_GRID) {
        int bx = blockIdx.x & 15;        // 16 N-blocks
        int by = blockIdx.x >> 4;        // 157 M-blocks
        gemm_core<true, true, true>(
            g_Yh, g_Yl, YS, g_W1h, g_W1l, YS,
            nullptr, g_X1h, g_X1l, FHID, b1, NNODES, YS / 32, bx, by, smem);
    } else if (blockIdx.x < G1_GRID + 256) {
        int idx = (blockIdx.x - G1_GRID) * 256 + threadIdx.x;   // 0..65535
        float acc = 0.f;
        #pragma unroll
        for (int s = 0; s < NSPLIT; s++)
            acc += g_T1p[(size_t)s * (BBATCH * FHID) + idx];
        __nv_bfloat16 h = __float2bfloat16_rn(acc);
        __nv_bfloat16 l = __float2bfloat16_rn(acc - __bfloat162float(h));
        g_T1h[idx] = h;
        g_T1l[idx] = l;
    } else {
        int wid = threadIdx.x >> 5, lane = threadIdx.x & 31;
        for (int i = 0; i < 8; i++) {
            int b = wid * 8 + i;
            float acc = 0.f;
            for (int k = lane; k < FOUT; k += 32)
                acc += img[(size_t)b * FOUT + k] * b2[k];
            #pragma unroll
            for (int off = 16; off > 0; off >>= 1)
                acc += __shfl_down_sync(0xffffffffu, acc, off);
            if (lane == 0) g_imgb2[b] = acc;
        }
    }
}

// ---------------- launch 6: T2 = X1 @ T1^T ----------------
__global__ void __launch_bounds__(256, 2) k_t2() {
    extern __shared__ char smem[];
    gemm_core<false, false, false>(
        g_X1h, g_X1l, FHID, g_T1h, g_T1l, FHID,
        g_T2, nullptr, nullptr, BBATCH, nullptr, NNODES, FHID / 32, 0, blockIdx.x, smem);
}

// ---------------- launch 7: output aggregation + fused transpose -------------
__global__ void __launch_bounds__(256) k_aggOutT(float* __restrict__ out) {
    __shared__ float s[32][65];
    int n0 = blockIdx.x * 32;
    int tid = threadIdx.x;
    int slot = tid >> 6;
    int b = tid & 63;
    float bias = g_imgb2[b];
    for (int rnd = 0; rnd < 8; rnd++) {
        int nl = rnd * 4 + slot;
        int n = n0 + nl;
        float acc = bias;
        int st = g_rowptr[n], en = g_rowptr[n + 1];
        for (int e = st; e < en; e++)
            acc += g_colw[e] * g_T2[(size_t)g_colsrc[e] * BBATCH + b];
        s[nl][b] = acc;
    }
    __syncthreads();
    #pragma unroll
    for (int i = 0; i < 8; i++) {
        int idx = tid + i * 256;
        int bb = idx >> 5, nn = idx & 31;
        out[(size_t)bb * NNODES + n0 + nn] = s[nn][bb];
    }
}

// ---------------- launch ----------------
extern "C" void kernel_launch(void* const* d_in, const int* in_sizes, int n_in,
                              void* d_out, int out_size) {
    const float* img  = (const float*)d_in[0];
    const float* nf   = (const float*)d_in[1];
    const int*   esrc = (const int*)d_in[2];
    const int*   edst = (const int*)d_in[3];
    const float* ew   = (const float*)d_in[4];
    const float* W1   = (const float*)d_in[5];
    const float* b1   = (const float*)d_in[6];
    const float* W2   = (const float*)d_in[7];
    const float* b2   = (const float*)d_in[8];
    float* out = (float*)d_out;

    const int SMEM = 92160;  // 3 stages x 30720
    cudaFuncSetAttribute(k_l5, cudaFuncAttributeMaxDynamicSharedMemorySize, SMEM);
    cudaFuncSetAttribute(k_t2, cudaFuncAttributeMaxDynamicSharedMemorySize, SMEM);

    // 0: zero scratch + split-transpose W1
    k_init<<<79 + 320, 256>>>(W1);
    // 1: degrees
    k_deg<<<(NEDGES + 255) / 256, 256>>>(edst, ew);
    // 2: scan + dinv
    k_scandinv<<<1, 1024>>>();
    // 3: CSR fill
    k_fill<<<(NEDGES + 255) / 256, 256>>>(esrc, edst, ew);
    // 4: aggY (split bf16) + T1 split-K partials
    k_agg_t1<<<AGG_BLKS + 16 * NSPLIT, 256>>>(nf, img, W2);
    // 5: GEMM1 + T1 reduce + imgb2
    k_l5<<<G1_GRID + 256 + 1, 256, SMEM>>>(b1, img, b2);
    // 6: T2
    k_t2<<<157, 256, SMEM>>>();
    // 7: output aggregation + fused transpose
    k_aggOutT<<<NNODES / 32, 256>>>(out);
}

// round 7
// speedup vs baseline: 1.0220x; 1.0220x over previous
#include <cuda_runtime.h>
#include <cuda_bf16.h>
#include <cstdint>

#define NNODES 20000
#define NEDGES 160000
#define BBATCH 64
#define FTEXT  300
#define YS     320          // padded K for layer-1 GEMM operands (zero-filled)
#define FHID   1024
#define FOUT   1664
#define NEG_SLOPE 0.2f
#define NSPLIT 13           // T1 split-K factor (13 * 128 = 1664)

// ---------------- scratch ----------------
__device__ float g_deg[NNODES];
__device__ float g_dinv[NNODES];
__device__ int   g_cnt[NNODES];
__device__ int   g_rowptr[NNODES + 1];
__device__ int   g_cursor[NNODES];
__device__ int   g_colsrc[NEDGES];
__device__ float g_colw[NEDGES];
__device__ __nv_bfloat16 g_Yh[(size_t)NNODES * YS];
__device__ __nv_bfloat16 g_Yl[(size_t)NNODES * YS];
__device__ __nv_bfloat16 g_W1h[(size_t)FHID * YS];
__device__ __nv_bfloat16 g_W1l[(size_t)FHID * YS];
__device__ __nv_bfloat16 g_X1h[(size_t)NNODES * FHID];
__device__ __nv_bfloat16 g_X1l[(size_t)NNODES * FHID];
__device__ float g_T1p[(size_t)NSPLIT * BBATCH * FHID];
__device__ __nv_bfloat16 g_T1h[BBATCH * FHID];
__device__ __nv_bfloat16 g_T1l[BBATCH * FHID];
__device__ float g_T2[(size_t)NNODES * BBATCH];
__device__ float g_imgb2[BBATCH];

// ---------------- PTX helpers (sm_80+ baseline only) ----------------
__device__ __forceinline__ uint32_t smem_to_u32(const void* p) {
    uint32_t a;
    asm("{ .reg .u64 t; cvta.to.shared.u64 t, %1; cvt.u32.u64 %0, t; }" : "=r"(a) : "l"(p));
    return a;
}
__device__ __forceinline__ void ldsm_x4(uint32_t* r, uint32_t addr) {
    asm volatile("ldmatrix.sync.aligned.m8n8.x4.shared.b16 {%0,%1,%2,%3}, [%4];"
        : "=r"(r[0]), "=r"(r[1]), "=r"(r[2]), "=r"(r[3]) : "r"(addr));
}
__device__ __forceinline__ void mma_bf16(float* c, const uint32_t* a, const uint32_t* b) {
    asm volatile(
        "mma.sync.aligned.m16n8k16.row.col.f32.bf16.bf16.f32 "
        "{%0,%1,%2,%3}, {%4,%5,%6,%7}, {%8,%9}, {%0,%1,%2,%3};"
        : "+f"(c[0]), "+f"(c[1]), "+f"(c[2]), "+f"(c[3])
        : "r"(a[0]), "r"(a[1]), "r"(a[2]), "r"(a[3]), "r"(b[0]), "r"(b[1]));
}

// ---------------- launch 0: zero scratch + split-transpose W1 ----------------
__global__ void k_init(const float* __restrict__ W1) {
    const int ZBLK = 79;
    int tid = threadIdx.x;
    if (blockIdx.x < ZBLK) {
        int i = blockIdx.x * 256 + tid;
        if (i < NNODES) { g_deg[i] = 0.f; g_cnt[i] = 0; g_cursor[i] = 0; }
    } else {
        __shared__ float s[32][33];
        int bidx = blockIdx.x - ZBLK;          // 0..319 (32 n-tiles x 10 k-tiles)
        int n0 = (bidx & 31) * 32;
        int k0 = (bidx >> 5) * 32;             // 0..288
        int tx = tid & 31, ty = tid >> 5;
        #pragma unroll
        for (int i = 0; i < 32; i += 8) {
            int k = k0 + ty + i, n = n0 + tx;
            s[ty + i][tx] = (k < FTEXT) ? W1[(size_t)k * FHID + n] : 0.f;
        }
        __syncthreads();
        #pragma unroll
        for (int i = 0; i < 32; i += 8) {
            int n = n0 + ty + i, k = k0 + tx;
            float v = s[tx][ty + i];
            __nv_bfloat16 h = __float2bfloat16_rn(v);
            __nv_bfloat16 l = __float2bfloat16_rn(v - __bfloat162float(h));
            g_W1h[(size_t)n * YS + k] = h;
            g_W1l[(size_t)n * YS + k] = l;
        }
    }
}

// ---------------- launch 1: degree ----------------
__global__ void k_deg(const int* __restrict__ dst, const float* __restrict__ w) {
    int e = blockIdx.x * blockDim.x + threadIdx.x;
    if (e < NEDGES) {
        int d = dst[e];
        atomicAdd(&g_deg[d], w[e]);
        atomicAdd(&g_cnt[d], 1);
    }
}

// ---------------- launch 2: warp-shuffle scan + dinv ----------------
__global__ void k_scandinv() {
    const int CH = 20;
    __shared__ int wtot[32];
    __shared__ int s_total;
    int t = threadIdx.x;
    int lane = t & 31, wid = t >> 5;
    int base = t * CH;
    int loc[CH];
    int sum = 0;
    #pragma unroll
    for (int i = 0; i < CH; i++) {
        int idx = base + i;
        int v = 0;
        if (idx < NNODES) {
            v = g_cnt[idx];
            float d = g_deg[idx];
            g_dinv[idx] = (d > 0.f) ? rsqrtf(d) : 0.f;
        }
        loc[i] = sum;
        sum += v;
    }
    int inc = sum;
    #pragma unroll
    for (int off = 1; off < 32; off <<= 1) {
        int v = __shfl_up_sync(0xffffffffu, inc, off);
        if (lane >= off) inc += v;
    }
    if (lane == 31) wtot[wid] = inc;
    __syncthreads();
    if (wid == 0) {
        int v = wtot[lane];
        int wi = v;
        #pragma unroll
        for (int off = 1; off < 32; off <<= 1) {
            int u = __shfl_up_sync(0xffffffffu, wi, off);
            if (lane >= off) wi += u;
        }
        wtot[lane] = wi - v;
        if (lane == 31) s_total = wi;
    }
    __syncthreads();
    int off0 = wtot[wid] + inc - sum;
    #pragma unroll
    for (int i = 0; i < CH; i++) {
        int idx = base + i;
        if (idx < NNODES) g_rowptr[idx] = off0 + loc[i];
    }
    if (t == 0) g_rowptr[NNODES] = s_total;
}

// ---------------- launch 3: fill CSR ----------------
__global__ void k_fill(const int* __restrict__ src, const int* __restrict__ dst,
                       const float* __restrict__ w) {
    int e = blockIdx.x * blockDim.x + threadIdx.x;
    if (e < NEDGES) {
        int s = src[e], d = dst[e];
        float nm = g_dinv[s] * w[e] * g_dinv[d];
        int pos = g_rowptr[d] + atomicAdd(&g_cursor[d], 1);
        g_colsrc[pos] = s;
        g_colw[pos]   = nm;
    }
}

// ---------------- launch 4: Y = A @ X (width 300), split bf16 out ------------
__global__ void k_aggY(const float* __restrict__ X) {
    __shared__ int   ss[128];
    __shared__ float sw[128];
    int n = blockIdx.x;
    int tid = threadIdx.x;
    int st = g_rowptr[n], en = g_rowptr[n + 1];
    float acc0 = 0.f, acc1 = 0.f, acc2 = 0.f;
    for (int e0 = st; e0 < en; e0 += 128) {
        int ne = min(128, en - e0);
        if (tid < ne) { ss[tid] = g_colsrc[e0 + tid]; sw[tid] = g_colw[e0 + tid]; }
        __syncthreads();
        for (int j = 0; j < ne; j++) {
            const float* xr = X + (size_t)ss[j] * FTEXT;
            float wv = sw[j];
            acc0 += wv * xr[tid];
            acc1 += wv * xr[tid + 128];
            if (tid + 256 < FTEXT) acc2 += wv * xr[tid + 256];
        }
        __syncthreads();
    }
    size_t rb = (size_t)n * YS;
    float v[3] = {acc0, acc1, acc2};
    #pragma unroll
    for (int q = 0; q < 3; q++) {
        int col = tid + q * 128;
        if (col < FTEXT) {
            __nv_bfloat16 h = __float2bfloat16_rn(v[q]);
            __nv_bfloat16 l = __float2bfloat16_rn(v[q] - __bfloat162float(h));
            g_Yh[rb + col] = h;
            g_Yl[rb + col] = l;
        }
    }
    if (tid < YS - FTEXT) {            // zero K pad 300..319
        g_Yh[rb + FTEXT + tid] = __nv_bfloat16(0.f);
        g_Yl[rb + FTEXT + tid] = __nv_bfloat16(0.f);
    }
}

// ---------------- bf16x3 mma.sync GEMM, pre-split operands -------------------
// C = (Ah+Al)[M,K] @ (Bh+Bl)[N,K]^T with hh+hl+lh accumulation.
// CTA tile 128x64, BK=32, reg-prefetch double buffer (R4 pipeline). K%32==0.
template<bool BIAS, bool LEAKY, bool SPLIT_OUT>
__global__ void __launch_bounds__(256, 2) mma_gemm(
    const __nv_bfloat16* __restrict__ Ah, const __nv_bfloat16* __restrict__ Al, int lda,
    const __nv_bfloat16* __restrict__ Bh, const __nv_bfloat16* __restrict__ Bl, int ldb,
    float* __restrict__ C, __nv_bfloat16* __restrict__ Ch, __nv_bfloat16* __restrict__ Cl,
    int ldc, const float* __restrict__ bias, int M, int K)
{
    extern __shared__ char smem[];
    const int A_BYTES = 128 * 80;           // 32 bf16/row at 80 B stride
    const int B_BYTES = 64 * 80;
    const int STAGE   = 2 * A_BYTES + 2 * B_BYTES;   // 30720

    int tid  = threadIdx.x;
    int wid  = tid >> 5, lane = tid & 31;
    int wm   = wid & 3, wn = wid >> 2;
    int row0 = blockIdx.y * 128;
    int col0 = blockIdx.x * 64;
    uint32_t smem_u = smem_to_u32(smem);

    float acc[2][4][4];
    #pragma unroll
    for (int mt = 0; mt < 2; mt++)
        #pragma unroll
        for (int nt = 0; nt < 4; nt++)
            #pragma unroll
            for (int q = 0; q < 4; q++) acc[mt][nt][q] = 0.f;

    uint4 aRh[2], aRl[2], bRh, bRl;
    const int nT = K >> 5;

    // per-thread copy coordinates (8 bf16 = 16 B per access)
    int ar = tid >> 2, ac8 = (tid & 3) * 8;     // A: rows ar, ar+64
    int br = tid >> 2, bc8 = (tid & 3) * 8;     // B: row br

    auto LDG = [&](int t) {
        int kb = t * 32;
        #pragma unroll
        for (int i = 0; i < 2; i++) {
            int row = row0 + ar + i * 64;
            row = (row < M) ? row : (M - 1);
            size_t off = (size_t)row * lda + kb + ac8;
            aRh[i] = *(const uint4*)(Ah + off);
            aRl[i] = *(const uint4*)(Al + off);
        }
        {
            size_t off = (size_t)(col0 + br) * ldb + kb + bc8;
            bRh = *(const uint4*)(Bh + off);
            bRl = *(const uint4*)(Bl + off);
        }
    };
    auto STS = [&](int s) {
        char* base = smem + s * STAGE;
        #pragma unroll
        for (int i = 0; i < 2; i++) {
            int r = ar + i * 64;
            *(uint4*)(base + r * 80 + ac8 * 2) = aRh[i];
            *(uint4*)(base + A_BYTES + r * 80 + ac8 * 2) = aRl[i];
        }
        *(uint4*)(base + 2 * A_BYTES + br * 80 + bc8 * 2) = bRh;
        *(uint4*)(base + 2 * A_BYTES + B_BYTES + br * 80 + bc8 * 2) = bRl;
    };
    auto COMPUTE = [&](int s) {
        uint32_t sb = smem_u + s * STAGE;
        uint32_t aH = sb + (uint32_t)((wm * 32 + (lane & 15)) * 80 + (lane >> 4) * 16);
        uint32_t aL = aH + A_BYTES;
        uint32_t bH = sb + 2 * A_BYTES +
            (uint32_t)((wn * 32 + ((lane >> 4) & 1) * 8 + (lane & 7)) * 80 + ((lane >> 3) & 1) * 16);
        uint32_t bL = bH + B_BYTES;
        #pragma unroll
        for (int ks = 0; ks < 2; ks++) {
            uint32_t ah[2][4], al[2][4], bh[2][4], bl[2][4];
            #pragma unroll
            for (int mt = 0; mt < 2; mt++) {
                ldsm_x4(ah[mt], aH + mt * 16 * 80 + ks * 32);
                ldsm_x4(al[mt], aL + mt * 16 * 80 + ks * 32);
            }
            #pragma unroll
            for (int g = 0; g < 2; g++) {
                ldsm_x4(bh[g], bH + g * 16 * 80 + ks * 32);
                ldsm_x4(bl[g], bL + g * 16 * 80 + ks * 32);
            }
            #pragma unroll
            for (int mt = 0; mt < 2; mt++)
                #pragma unroll
                for (int nt = 0; nt < 4; nt++) {
                    const uint32_t* ph = &bh[nt >> 1][(nt & 1) * 2];
                    const uint32_t* pl = &bl[nt >> 1][(nt & 1) * 2];
                    mma_bf16(acc[mt][nt], ah[mt], ph);
                    mma_bf16(acc[mt][nt], ah[mt], pl);
                    mma_bf16(acc[mt][nt], al[mt], ph);
                }
        }
    };

    // R4 pipeline: reg-prefetch double buffer
    LDG(0);
    STS(0);
    if (nT > 1) LDG(1);
    __syncthreads();
    for (int t = 0; t < nT; t++) {
        COMPUTE(t & 1);
        if (t + 1 < nT) STS((t + 1) & 1);
        __syncthreads();
        if (t + 2 < nT) LDG(t + 2);
    }

    // epilogue
    int rw = row0 + wm * 32;
    int cw = col0 + wn * 32;
    #pragma unroll
    for (int mt = 0; mt < 2; mt++) {
        #pragma unroll
        for (int half = 0; half < 2; half++) {
            int row = rw + mt * 16 + (lane >> 2) + half * 8;
            if (row >= M) continue;
            #pragma unroll
            for (int nt = 0; nt < 4; nt++) {
                int col = cw + nt * 8 + (lane & 3) * 2;
                float v0 = acc[mt][nt][half * 2 + 0];
                float v1 = acc[mt][nt][half * 2 + 1];
                if (BIAS) { v0 += bias[col]; v1 += bias[col + 1]; }
                if (LEAKY) {
                    v0 = (v0 >= 0.f) ? v0 : NEG_SLOPE * v0;
                    v1 = (v1 >= 0.f) ? v1 : NEG_SLOPE * v1;
                }
                if (SPLIT_OUT) {
                    __nv_bfloat16 h0 = __float2bfloat16_rn(v0);
                    __nv_bfloat16 h1 = __float2bfloat16_rn(v1);
                    __nv_bfloat16 l0 = __float2bfloat16_rn(v0 - __bfloat162float(h0));
                    __nv_bfloat16 l1 = __float2bfloat16_rn(v1 - __bfloat162float(h1));
                    __nv_bfloat162 hp(h0, h1), lp(l0, l1);
                    *(uint32_t*)(Ch + (size_t)row * ldc + col) = *(uint32_t*)&hp;
                    *(uint32_t*)(Cl + (size_t)row * ldc + col) = *(uint32_t*)&lp;
                } else {
                    float2 o; o.x = v0; o.y = v1;
                    *(float2*)(C + (size_t)row * ldc + col) = o;
                }
            }
        }
    }
}

// ---------------- launch 6: T1 split-K SIMT fp32 ----------------
__global__ void __launch_bounds__(256) k_t1_splitk(
    const float* __restrict__ img, const float* __restrict__ W2)
{
    const int BK = 16;
    __shared__ float As[BK][64 + 1];
    __shared__ float Bs[BK][64 + 1];
    int tid = threadIdx.x;
    int tx = tid & 15, ty = tid >> 4;
    int col0 = blockIdx.x * 64;
    int s = blockIdx.y;
    int kbase = s * 128;

    float acc[4][4] = {};
    int r = tid >> 2, kq = (tid & 3) * 4;

    for (int t0 = 0; t0 < 128; t0 += BK) {
        float4 av = *(const float4*)(img + (size_t)r * FOUT + kbase + t0 + kq);
        As[kq + 0][r] = av.x; As[kq + 1][r] = av.y;
        As[kq + 2][r] = av.z; As[kq + 3][r] = av.w;
        float4 bv = *(const float4*)(W2 + (size_t)(col0 + r) * FOUT + kbase + t0 + kq);
        Bs[kq + 0][r] = bv.x; Bs[kq + 1][r] = bv.y;
        Bs[kq + 2][r] = bv.z; Bs[kq + 3][r] = bv.w;
        __syncthreads();
        #pragma unroll
        for (int k = 0; k < BK; k++) {
            float a[4], b[4];
            #pragma unroll
            for (int i = 0; i < 4; i++) a[i] = As[k][ty * 4 + i];
            #pragma unroll
            for (int j = 0; j < 4; j++) b[j] = Bs[k][tx * 4 + j];
            #pragma unroll
            for (int i = 0; i < 4; i++)
                #pragma unroll
                for (int j = 0; j < 4; j++)
                    acc[i][j] += a[i] * b[j];
        }
        __syncthreads();
    }
    float* cp = g_T1p + (size_t)s * (BBATCH * FHID);
    #pragma unroll
    for (int i = 0; i < 4; i++) {
        int b = ty * 4 + i;
        #pragma unroll
        for (int j = 0; j < 4; j++)
            cp[(size_t)b * FHID + col0 + tx * 4 + j] = acc[i][j];
    }
}

// ---------------- launch 7: reduce T1 partials (split out) + imgb2 -----------
__global__ void k_t1_reduce(const float* __restrict__ img, const float* __restrict__ b2) {
    if (blockIdx.x < 256) {
        int idx = blockIdx.x * 256 + threadIdx.x;
        float acc = 0.f;
        #pragma unroll
        for (int s = 0; s < NSPLIT; s++)
            acc += g_T1p[(size_t)s * (BBATCH * FHID) + idx];
        __nv_bfloat16 h = __float2bfloat16_rn(acc);
        __nv_bfloat16 l = __float2bfloat16_rn(acc - __bfloat162float(h));
        g_T1h[idx] = h;
        g_T1l[idx] = l;
    } else {
        int wid = threadIdx.x >> 5, lane = threadIdx.x & 31;
        for (int i = 0; i < 8; i++) {
            int b = wid * 8 + i;
            float acc = 0.f;
            for (int k = lane; k < FOUT; k += 32)
                acc += img[(size_t)b * FOUT + k] * b2[k];
            #pragma unroll
            for (int off = 16; off > 0; off >>= 1)
                acc += __shfl_down_sync(0xffffffffu, acc, off);
            if (lane == 0) g_imgb2[b] = acc;
        }
    }
}

// ---------------- launch 8: output aggregation + fused transpose -------------
__global__ void __launch_bounds__(256) k_aggOutT(float* __restrict__ out) {
    __shared__ float s[32][65];
    int n0 = blockIdx.x * 32;
    int tid = threadIdx.x;
    int slot = tid >> 6;
    int b = tid & 63;
    float bias = g_imgb2[b];
    for (int rnd = 0; rnd < 8; rnd++) {
        int nl = rnd * 4 + slot;
        int n = n0 + nl;
        float acc = bias;
        int st = g_rowptr[n], en = g_rowptr[n + 1];
        for (int e = st; e < en; e++)
            acc += g_colw[e] * g_T2[(size_t)g_colsrc[e] * BBATCH + b];
        s[nl][b] = acc;
    }
    __syncthreads();
    #pragma unroll
    for (int i = 0; i < 8; i++) {
        int idx = tid + i * 256;
        int bb = idx >> 5, nn = idx & 31;
        out[(size_t)bb * NNODES + n0 + nn] = s[nn][bb];
    }
}

// ---------------- launch ----------------
extern "C" void kernel_launch(void* const* d_in, const int* in_sizes, int n_in,
                              void* d_out, int out_size) {
    const float* img  = (const float*)d_in[0];
    const float* nf   = (const float*)d_in[1];
    const int*   esrc = (const int*)d_in[2];
    const int*   edst = (const int*)d_in[3];
    const float* ew   = (const float*)d_in[4];
    const float* W1   = (const float*)d_in[5];
    const float* b1   = (const float*)d_in[6];
    const float* W2   = (const float*)d_in[7];
    const float* b2   = (const float*)d_in[8];
    float* out = (float*)d_out;

    __nv_bfloat16 *dYh, *dYl, *dW1h, *dW1l, *dX1h, *dX1l, *dT1h, *dT1l;
    float* dT2;
    cudaGetSymbolAddress((void**)&dYh,  g_Yh);
    cudaGetSymbolAddress((void**)&dYl,  g_Yl);
    cudaGetSymbolAddress((void**)&dW1h, g_W1h);
    cudaGetSymbolAddress((void**)&dW1l, g_W1l);
    cudaGetSymbolAddress((void**)&dX1h, g_X1h);
    cudaGetSymbolAddress((void**)&dX1l, g_X1l);
    cudaGetSymbolAddress((void**)&dT1h, g_T1h);
    cudaGetSymbolAddress((void**)&dT1l, g_T1l);
    cudaGetSymbolAddress((void**)&dT2,  g_T2);

    const int SMEM = 61440;  // 2 stages x 30720
    cudaFuncSetAttribute(mma_gemm<true,  true,  true >, cudaFuncAttributeMaxDynamicSharedMemorySize, SMEM);
    cudaFuncSetAttribute(mma_gemm<false, false, false>, cudaFuncAttributeMaxDynamicSharedMemorySize, SMEM);

    // 0: zero scratch + split-transpose W1
    k_init<<<79 + 320, 256>>>(W1);
    // 1: degrees
    k_deg<<<(NEDGES + 255) / 256, 256>>>(edst, ew);
    // 2: scan + dinv
    k_scandinv<<<1, 1024>>>();
    // 3: CSR fill
    k_fill<<<(NEDGES + 255) / 256, 256>>>(esrc, edst, ew);
    // 4: layer-1 aggregation (width 300, split bf16 out)
    k_aggY<<<NNODES, 128>>>(nf);
    // 5: X1 = leaky(Y @ W1 + b1), split bf16 out  (device pointers, NOT symbols)
    {
        dim3 grid(FHID / 64, (NNODES + 127) / 128);
        mma_gemm<true, true, true><<<grid, 256, SMEM>>>(
            dYh, dYl, YS, dW1h, dW1l, YS,
            nullptr, dX1h, dX1l, FHID, b1, NNODES, YS);
    }
    // 6: T1 partials (split-K SIMT fp32)
    {
        dim3 grid(FHID / 64, NSPLIT);
        k_t1_splitk<<<grid, 256>>>(img, W2);
    }
    // 7: reduce T1 (split out) + imgb2
    k_t1_reduce<<<257, 256>>>(img, b2);
    // 8: T2 = X1 @ T1^T  (device pointers, NOT symbols)
    {
        dim3 grid(1, (NNODES + 127) / 128);
        mma_gemm<false, false, false><<<grid, 256, SMEM>>>(
            dX1h, dX1l, FHID, dT1h, dT1l, FHID,
            dT2, nullptr, nullptr, BBATCH, nullptr, NNODES, FHID);
    }
    // 9: output aggregation + fused transpose
    k_aggOutT<<<NNODES / 32, 256>>>(out);
}

// round 8
// speedup vs baseline: 1.0545x; 1.0319x over previous
#include <cuda_runtime.h>
#include <cuda_bf16.h>
#include <cstdint>

#define NNODES 20000
#define NEDGES 160000
#define BBATCH 64
#define FTEXT  300
#define FHID   1024
#define FOUT   1664
#define NEG_SLOPE 0.2f
#define NSPLIT 13          // T1 split-K factor (13 * 128 = 1664)

// ---------------- scratch ----------------
__device__ float g_deg[NNODES];
__device__ float g_dinv[NNODES];
__device__ int   g_cnt[NNODES];
__device__ int   g_rowptr[NNODES + 1];
__device__ int   g_cursor[NNODES];
__device__ int   g_colsrc[NEDGES];
__device__ float g_colw[NEDGES];
__device__ float g_Y[(size_t)NNODES * FTEXT];     // A @ X            [20000,300]
__device__ float g_X1[(size_t)NNODES * FHID];     // leaky(Y@W1+b1)   [20000,1024]
__device__ float g_W1t[(size_t)FHID * FTEXT];     // W1^T             [1024,300]
__device__ float g_T1p[(size_t)NSPLIT * BBATCH * FHID];
__device__ float g_T1[BBATCH * FHID];             // img @ W2^T       [64,1024]
__device__ float g_T2[(size_t)NNODES * BBATCH];   // X1 @ T1^T        [20000,64]
__device__ float g_imgb2[BBATCH];

// ---------------- PTX helpers (sm_80+ baseline only) ----------------
__device__ __forceinline__ uint32_t smem_to_u32(const void* p) {
    uint32_t a;
    asm("{ .reg .u64 t; cvta.to.shared.u64 t, %1; cvt.u32.u64 %0, t; }" : "=r"(a) : "l"(p));
    return a;
}
__device__ __forceinline__ void ldsm_x4(uint32_t* r, uint32_t addr) {
    asm volatile("ldmatrix.sync.aligned.m8n8.x4.shared.b16 {%0,%1,%2,%3}, [%4];"
        : "=r"(r[0]), "=r"(r[1]), "=r"(r[2]), "=r"(r[3]) : "r"(addr));
}
__device__ __forceinline__ void mma_bf16(float* c, const uint32_t* a, const uint32_t* b) {
    asm volatile(
        "mma.sync.aligned.m16n8k16.row.col.f32.bf16.bf16.f32 "
        "{%0,%1,%2,%3}, {%4,%5,%6,%7}, {%8,%9}, {%0,%1,%2,%3};"
        : "+f"(c[0]), "+f"(c[1]), "+f"(c[2]), "+f"(c[3])
        : "r"(a[0]), "r"(a[1]), "r"(a[2]), "r"(a[3]), "r"(b[0]), "r"(b[1]));
}
__device__ __forceinline__ void f4_hilo(float4 v, uint2& h, uint2& l) {
    __nv_bfloat16 hx = __float2bfloat16_rn(v.x);
    __nv_bfloat16 hy = __float2bfloat16_rn(v.y);
    __nv_bfloat16 hz = __float2bfloat16_rn(v.z);
    __nv_bfloat16 hw = __float2bfloat16_rn(v.w);
    __nv_bfloat16 lx = __float2bfloat16_rn(v.x - __bfloat162float(hx));
    __nv_bfloat16 ly = __float2bfloat16_rn(v.y - __bfloat162float(hy));
    __nv_bfloat16 lz = __float2bfloat16_rn(v.z - __bfloat162float(hz));
    __nv_bfloat16 lw = __float2bfloat16_rn(v.w - __bfloat162float(hw));
    __nv_bfloat162 h01(hx, hy), h23(hz, hw), l01(lx, ly), l23(lz, lw);
    h.x = *(uint32_t*)&h01; h.y = *(uint32_t*)&h23;
    l.x = *(uint32_t*)&l01; l.y = *(uint32_t*)&l23;
}

// ---------------- launch 0: zero scratch + transpose W1 (fp32) ---------------
__global__ void k_init(const float* __restrict__ W1) {
    const int ZBLK = 79;
    int tid = threadIdx.x;
    if (blockIdx.x < ZBLK) {
        int i = blockIdx.x * 256 + tid;
        if (i < NNODES) { g_deg[i] = 0.f; g_cnt[i] = 0; g_cursor[i] = 0; }
    } else {
        __shared__ float s[32][33];
        int bidx = blockIdx.x - ZBLK;          // 0..319 (32 n-tiles x 10 k-tiles)
        int n0 = (bidx & 31) * 32;
        int k0 = (bidx >> 5) * 32;
        int tx = tid & 31, ty = tid >> 5;
        #pragma unroll
        for (int i = 0; i < 32; i += 8) {
            int k = k0 + ty + i, n = n0 + tx;
            if (k < FTEXT) s[ty + i][tx] = W1[(size_t)k * FHID + n];
        }
        __syncthreads();
        #pragma unroll
        for (int i = 0; i < 32; i += 8) {
            int n = n0 + ty + i, k = k0 + tx;
            if (k < FTEXT) g_W1t[(size_t)n * FTEXT + k] = s[tx][ty + i];
        }
    }
}

// ---------------- launch 1: degree ----------------
__global__ void k_deg(const int* __restrict__ dst, const float* __restrict__ w) {
    int e = blockIdx.x * blockDim.x + threadIdx.x;
    if (e < NEDGES) {
        int d = dst[e];
        atomicAdd(&g_deg[d], w[e]);
        atomicAdd(&g_cnt[d], 1);
    }
}

// ---------------- launch 2: warp-shuffle scan + dinv ----------------
__global__ void k_scandinv() {
    const int CH = 20;
    __shared__ int wtot[32];
    __shared__ int s_total;
    int t = threadIdx.x;
    int lane = t & 31, wid = t >> 5;
    int base = t * CH;
    int loc[CH];
    int sum = 0;
    #pragma unroll
    for (int i = 0; i < CH; i++) {
        int idx = base + i;
        int v = 0;
        if (idx < NNODES) {
            v = g_cnt[idx];
            float d = g_deg[idx];
            g_dinv[idx] = (d > 0.f) ? rsqrtf(d) : 0.f;
        }
        loc[i] = sum;
        sum += v;
    }
    int inc = sum;
    #pragma unroll
    for (int off = 1; off < 32; off <<= 1) {
        int v = __shfl_up_sync(0xffffffffu, inc, off);
        if (lane >= off) inc += v;
    }
    if (lane == 31) wtot[wid] = inc;
    __syncthreads();
    if (wid == 0) {
        int v = wtot[lane];
        int wi = v;
        #pragma unroll
        for (int off = 1; off < 32; off <<= 1) {
            int u = __shfl_up_sync(0xffffffffu, wi, off);
            if (lane >= off) wi += u;
        }
        wtot[lane] = wi - v;
        if (lane == 31) s_total = wi;
    }
    __syncthreads();
    int off0 = wtot[wid] + inc - sum;
    #pragma unroll
    for (int i = 0; i < CH; i++) {
        int idx = base + i;
        if (idx < NNODES) g_rowptr[idx] = off0 + loc[i];
    }
    if (t == 0) g_rowptr[NNODES] = s_total;
}

// ---------------- launch 3: fill CSR ----------------
__global__ void k_fill(const int* __restrict__ src, const int* __restrict__ dst,
                       const float* __restrict__ w) {
    int e = blockIdx.x * blockDim.x + threadIdx.x;
    if (e < NEDGES) {
        int s = src[e], d = dst[e];
        float nm = g_dinv[s] * w[e] * g_dinv[d];
        int pos = g_rowptr[d] + atomicAdd(&g_cursor[d], 1);
        g_colsrc[pos] = s;
        g_colw[pos]   = nm;
    }
}

// ---------------- launch 4: Y = A @ X (width 300, fp32 out), unroll x2 -------
__global__ void k_aggY(const float* __restrict__ X) {
    __shared__ int   ss[128];
    __shared__ float sw[128];
    int n = blockIdx.x;
    int tid = threadIdx.x;
    int st = g_rowptr[n], en = g_rowptr[n + 1];
    float acc0 = 0.f, acc1 = 0.f, acc2 = 0.f;
    bool has2 = (tid + 256 < FTEXT);
    for (int e0 = st; e0 < en; e0 += 128) {
        int ne = min(128, en - e0);
        if (tid < ne) { ss[tid] = g_colsrc[e0 + tid]; sw[tid] = g_colw[e0 + tid]; }
        __syncthreads();
        int j = 0;
        for (; j + 2 <= ne; j += 2) {
            const float* x0 = X + (size_t)ss[j] * FTEXT;
            const float* x1 = X + (size_t)ss[j + 1] * FTEXT;
            float w0 = sw[j], w1 = sw[j + 1];
            float p0 = x0[tid], q0 = x1[tid];
            float p1 = x0[tid + 128], q1 = x1[tid + 128];
            float p2 = 0.f, q2 = 0.f;
            if (has2) { p2 = x0[tid + 256]; q2 = x1[tid + 256]; }
            acc0 += w0 * p0; acc1 += w0 * p1; acc2 += w0 * p2;
            acc0 += w1 * q0; acc1 += w1 * q1; acc2 += w1 * q2;
        }
        if (j < ne) {
            const float* x0 = X + (size_t)ss[j] * FTEXT;
            float w0 = sw[j];
            acc0 += w0 * x0[tid];
            acc1 += w0 * x0[tid + 128];
            if (has2) acc2 += w0 * x0[tid + 256];
        }
        __syncthreads();
    }
    float* yr = g_Y + (size_t)n * FTEXT;
    yr[tid] = acc0;
    yr[tid + 128] = acc1;
    if (has2) yr[tid + 256] = acc2;
}

// ---------------- launch 5: GEMM1, CTA tile 128x128, 512 threads -------------
// X1 = leaky(Y @ W1t^T + b1); Y [20000,300], W1t [1024,300]; bf16x3 in-STS split.
__global__ void __launch_bounds__(512, 1) k_gemm1(
    const float* __restrict__ A, const float* __restrict__ B,
    float* __restrict__ C, const float* __restrict__ bias)
{
    extern __shared__ char smem[];
    const int TB = 10240;                  // one 128x32-bf16 buffer @80B stride
    const int STAGE = 4 * TB;              // Ah Al Bh Bl
    const int M = NNODES, K = FTEXT;

    int tid = threadIdx.x;
    int wid = tid >> 5, lane = tid & 31;
    int wm = wid & 3, wn = wid >> 2;       // 4x4 warps, 32x32 each
    int row0 = blockIdx.y * 128;
    int col0 = blockIdx.x * 128;
    uint32_t smem_u = smem_to_u32(smem);

    float acc[2][4][4];
    #pragma unroll
    for (int mt = 0; mt < 2; mt++)
        #pragma unroll
        for (int nt = 0; nt < 4; nt++)
            #pragma unroll
            for (int q = 0; q < 4; q++) acc[mt][nt][q] = 0.f;

    float4 aR[2], bR[2];
    const int nT = 10;                     // ceil(300/32)

    auto LDG = [&](int t) {
        int kb = t * 32;
        #pragma unroll
        for (int i = 0; i < 2; i++) {
            int idx = tid + i * 512;       // 0..1023 float4s
            int r = idx >> 3, kg = kb + (idx & 7) * 4;
            int row = row0 + r; row = (row < M) ? row : (M - 1);
            float4 v = make_float4(0.f, 0.f, 0.f, 0.f);
            float4 w = make_float4(0.f, 0.f, 0.f, 0.f);
            if (kg + 4 <= K) {             // K%4==0: float4 fully valid or not
                v = *(const float4*)(A + (size_t)row * K + kg);
                w = *(const float4*)(B + (size_t)(col0 + r) * K + kg);
            }
            aR[i] = v; bR[i] = w;
        }
    };
    auto STS = [&](int s) {
        char* base = smem + s * STAGE;
        #pragma unroll
        for (int i = 0; i < 2; i++) {
            int idx = tid + i * 512;
            int r = idx >> 3, c8 = (idx & 7) * 8;   // byte offset within row
            uint2 h, l;
            f4_hilo(aR[i], h, l);
            *(uint2*)(base + r * 80 + c8) = h;
            *(uint2*)(base + TB + r * 80 + c8) = l;
            f4_hilo(bR[i], h, l);
            *(uint2*)(base + 2 * TB + r * 80 + c8) = h;
            *(uint2*)(base + 3 * TB + r * 80 + c8) = l;
        }
    };
    auto COMPUTE = [&](int s) {
        uint32_t sb = smem_u + s * STAGE;
        uint32_t aH = sb + (uint32_t)((wm * 32 + (lane & 15)) * 80 + (lane >> 4) * 16);
        uint32_t aL = aH + TB;
        uint32_t bH = sb + 2 * TB +
            (uint32_t)((wn * 32 + ((lane >> 4) & 1) * 8 + (lane & 7)) * 80 + ((lane >> 3) & 1) * 16);
        uint32_t bL = bH + TB;
        #pragma unroll
        for (int ks = 0; ks < 2; ks++) {
            uint32_t ah[2][4], al[2][4], bh[2][4], bl[2][4];
            #pragma unroll
            for (int mt = 0; mt < 2; mt++) {
                ldsm_x4(ah[mt], aH + mt * 16 * 80 + ks * 32);
                ldsm_x4(al[mt], aL + mt * 16 * 80 + ks * 32);
            }
            #pragma unroll
            for (int g = 0; g < 2; g++) {
                ldsm_x4(bh[g], bH + g * 16 * 80 + ks * 32);
                ldsm_x4(bl[g], bL + g * 16 * 80 + ks * 32);
            }
            #pragma unroll
            for (int mt = 0; mt < 2; mt++)
                #pragma unroll
                for (int nt = 0; nt < 4; nt++) {
                    const uint32_t* ph = &bh[nt >> 1][(nt & 1) * 2];
                    const uint32_t* pl = &bl[nt >> 1][(nt & 1) * 2];
                    mma_bf16(acc[mt][nt], ah[mt], ph);
                    mma_bf16(acc[mt][nt], ah[mt], pl);
                    mma_bf16(acc[mt][nt], al[mt], ph);
                }
        }
    };

    LDG(0);
    STS(0);
    LDG(1);
    __syncthreads();
    for (int t = 0; t < nT; t++) {
        COMPUTE(t & 1);
        if (t + 1 < nT) STS((t + 1) & 1);
        __syncthreads();
        if (t + 2 < nT) LDG(t + 2);
    }

    int rw = row0 + wm * 32;
    int cw = col0 + wn * 32;
    #pragma unroll
    for (int mt = 0; mt < 2; mt++) {
        #pragma unroll
        for (int half = 0; half < 2; half++) {
            int row = rw + mt * 16 + (lane >> 2) + half * 8;
            if (row >= M) continue;
            #pragma unroll
            for (int nt = 0; nt < 4; nt++) {
                int col = cw + nt * 8 + (lane & 3) * 2;
                float v0 = acc[mt][nt][half * 2 + 0] + bias[col];
                float v1 = acc[mt][nt][half * 2 + 1] + bias[col + 1];
                v0 = (v0 >= 0.f) ? v0 : NEG_SLOPE * v0;
                v1 = (v1 >= 0.f) ? v1 : NEG_SLOPE * v1;
                float2 o; o.x = v0; o.y = v1;
                *(float2*)(C + (size_t)row * FHID + col) = o;
            }
        }
    }
}

// ---------------- T2 GEMM (R4 mma_gemm, 256 thr, BN=64) ----------------------
template<bool BIAS, bool LEAKY>
__global__ void __launch_bounds__(256, 2) mma_gemm(
    const float* __restrict__ A, int lda,
    const float* __restrict__ B, int ldb,
    float* __restrict__ C, int ldc,
    const float* __restrict__ bias,
    int M, int N, int K)
{
    extern __shared__ char smem[];
    const int A_BYTES = 128 * 80;
    const int B_BYTES = 64 * 80;
    const int STAGE   = 2 * A_BYTES + 2 * B_BYTES;

    int tid  = threadIdx.x;
    int wid  = tid >> 5, lane = tid & 31;
    int wm   = wid & 3, wn = wid >> 2;
    int row0 = blockIdx.y * 128;
    int col0 = blockIdx.x * 64;
    uint32_t smem_u = smem_to_u32(smem);

    float acc[2][4][4];
    #pragma unroll
    for (int mt = 0; mt < 2; mt++)
        #pragma unroll
        for (int nt = 0; nt < 4; nt++)
            #pragma unroll
            for (int q = 0; q < 4; q++) acc[mt][nt][q] = 0.f;

    float4 aR[4], bR[2];
    const int nT = (K + 31) >> 5;

    auto LDG = [&](int t) {
        int kb = t * 32;
        #pragma unroll
        for (int i = 0; i < 4; i++) {
            int idx = tid + i * 256;
            int r = idx >> 3, kk = (idx & 7) * 4;
            int row = row0 + r, kg = kb + kk;
            float4 v = make_float4(0.f, 0.f, 0.f, 0.f);
            if (row < M && kg < K) v = *(const float4*)(A + (size_t)row * lda + kg);
            aR[i] = v;
        }
        #pragma unroll
        for (int i = 0; i < 2; i++) {
            int idx = tid + i * 256;
            int c = idx >> 3, kk = (idx & 7) * 4;
            int col = col0 + c, kg = kb + kk;
            float4 v = make_float4(0.f, 0.f, 0.f, 0.f);
            if (col < N && kg < K) v = *(const float4*)(B + (size_t)col * ldb + kg);
            bR[i] = v;
        }
    };
    auto STS = [&](int s) {
        char* base = smem + s * STAGE;
        #pragma unroll
        for (int i = 0; i < 4; i++) {
            int idx = tid + i * 256;
            int r = idx >> 3, kk = (idx & 7) * 4;
            uint2 h, l;
            f4_hilo(aR[i], h, l);
            *(uint2*)(base + r * 80 + kk * 2) = h;
            *(uint2*)(base + A_BYTES + r * 80 + kk * 2) = l;
        }
        #pragma unroll
        for (int i = 0; i < 2; i++) {
            int idx = tid + i * 256;
            int c = idx >> 3, kk = (idx & 7) * 4;
            uint2 h, l;
            f4_hilo(bR[i], h, l);
            *(uint2*)(base + 2 * A_BYTES + c * 80 + kk * 2) = h;
            *(uint2*)(base + 2 * A_BYTES + B_BYTES + c * 80 + kk * 2) = l;
        }
    };
    auto COMPUTE = [&](int s) {
        uint32_t sb = smem_u + s * STAGE;
        uint32_t aH = sb + (uint32_t)((wm * 32 + (lane & 15)) * 80 + (lane >> 4) * 16);
        uint32_t aL = aH + A_BYTES;
        uint32_t bH = sb + 2 * A_BYTES +
            (uint32_t)((wn * 32 + ((lane >> 4) & 1) * 8 + (lane & 7)) * 80 + ((lane >> 3) & 1) * 16);
        uint32_t bL = bH + B_BYTES;
        #pragma unroll
        for (int ks = 0; ks < 2; ks++) {
            uint32_t ah[2][4], al[2][4], bh[2][4], bl[2][4];
            #pragma unroll
            for (int mt = 0; mt < 2; mt++) {
                ldsm_x4(ah[mt], aH + mt * 16 * 80 + ks * 32);
                ldsm_x4(al[mt], aL + mt * 16 * 80 + ks * 32);
            }
            #pragma unroll
            for (int g = 0; g < 2; g++) {
                ldsm_x4(bh[g], bH + g * 16 * 80 + ks * 32);
                ldsm_x4(bl[g], bL + g * 16 * 80 + ks * 32);
            }
            #pragma unroll
            for (int mt = 0; mt < 2; mt++)
                #pragma unroll
                for (int nt = 0; nt < 4; nt++) {
                    const uint32_t* ph = &bh[nt >> 1][(nt & 1) * 2];
                    const uint32_t* pl = &bl[nt >> 1][(nt & 1) * 2];
                    mma_bf16(acc[mt][nt], ah[mt], ph);
                    mma_bf16(acc[mt][nt], ah[mt], pl);
                    mma_bf16(acc[mt][nt], al[mt], ph);
                }
        }
    };

    LDG(0);
    STS(0);
    if (nT > 1) LDG(1);
    __syncthreads();
    for (int t = 0; t < nT; t++) {
        COMPUTE(t & 1);
        if (t + 1 < nT) STS((t + 1) & 1);
        __syncthreads();
        if (t + 2 < nT) LDG(t + 2);
    }

    int rw = row0 + wm * 32;
    int cw = col0 + wn * 32;
    #pragma unroll
    for (int mt = 0; mt < 2; mt++) {
        #pragma unroll
        for (int half = 0; half < 2; half++) {
            int row = rw + mt * 16 + (lane >> 2) + half * 8;
            if (row >= M) continue;
            #pragma unroll
            for (int nt = 0; nt < 4; nt++) {
                int col = cw + nt * 8 + (lane & 3) * 2;
                if (col >= N) continue;
                float v0 = acc[mt][nt][half * 2 + 0];
                float v1 = acc[mt][nt][half * 2 + 1];
                if (BIAS) { v0 += bias[col]; v1 += bias[col + 1]; }
                if (LEAKY) {
                    v0 = (v0 >= 0.f) ? v0 : NEG_SLOPE * v0;
                    v1 = (v1 >= 0.f) ? v1 : NEG_SLOPE * v1;
                }
                float2 o; o.x = v0; o.y = v1;
                *(float2*)(C + (size_t)row * ldc + col) = o;
            }
        }
    }
}

// ---------------- launch 6: T1 split-K SIMT fp32 ----------------
__global__ void __launch_bounds__(256) k_t1_splitk(
    const float* __restrict__ img, const float* __restrict__ W2)
{
    const int BK = 16;
    __shared__ float As[BK][64 + 1];
    __shared__ float Bs[BK][64 + 1];
    int tid = threadIdx.x;
    int tx = tid & 15, ty = tid >> 4;
    int col0 = blockIdx.x * 64;
    int s = blockIdx.y;
    int kbase = s * 128;

    float acc[4][4] = {};
    int r = tid >> 2, kq = (tid & 3) * 4;

    for (int t0 = 0; t0 < 128; t0 += BK) {
        float4 av = *(const float4*)(img + (size_t)r * FOUT + kbase + t0 + kq);
        As[kq + 0][r] = av.x; As[kq + 1][r] = av.y;
        As[kq + 2][r] = av.z; As[kq + 3][r] = av.w;
        float4 bv = *(const float4*)(W2 + (size_t)(col0 + r) * FOUT + kbase + t0 + kq);
        Bs[kq + 0][r] = bv.x; Bs[kq + 1][r] = bv.y;
        Bs[kq + 2][r] = bv.z; Bs[kq + 3][r] = bv.w;
        __syncthreads();
        #pragma unroll
        for (int k = 0; k < BK; k++) {
            float a[4], b[4];
            #pragma unroll
            for (int i = 0; i < 4; i++) a[i] = As[k][ty * 4 + i];
            #pragma unroll
            for (int j = 0; j < 4; j++) b[j] = Bs[k][tx * 4 + j];
            #pragma unroll
            for (int i = 0; i < 4; i++)
                #pragma unroll
                for (int j = 0; j < 4; j++)
                    acc[i][j] += a[i] * b[j];
        }
        __syncthreads();
    }
    float* cp = g_T1p + (size_t)s * (BBATCH * FHID);
    #pragma unroll
    for (int i = 0; i < 4; i++) {
        int b = ty * 4 + i;
        #pragma unroll
        for (int j = 0; j < 4; j++)
            cp[(size_t)b * FHID + col0 + tx * 4 + j] = acc[i][j];
    }
}

// ---------------- launch 7: reduce T1 partials + imgb2 ----------------
__global__ void k_t1_reduce(const float* __restrict__ img, const float* __restrict__ b2) {
    if (blockIdx.x < 256) {
        int idx = blockIdx.x * 256 + threadIdx.x;
        float acc = 0.f;
        #pragma unroll
        for (int s = 0; s < NSPLIT; s++)
            acc += g_T1p[(size_t)s * (BBATCH * FHID) + idx];
        g_T1[idx] = acc;
    } else {
        int wid = threadIdx.x >> 5, lane = threadIdx.x & 31;
        for (int i = 0; i < 8; i++) {
            int b = wid * 8 + i;
            float acc = 0.f;
            for (int k = lane; k < FOUT; k += 32)
                acc += img[(size_t)b * FOUT + k] * b2[k];
            #pragma unroll
            for (int off = 16; off > 0; off >>= 1)
                acc += __shfl_down_sync(0xffffffffu, acc, off);
            if (lane == 0) g_imgb2[b] = acc;
        }
    }
}

// ---------------- launch 9: output aggregation + fused transpose -------------
__global__ void __launch_bounds__(256) k_aggOutT(float* __restrict__ out) {
    __shared__ float s[32][65];
    int n0 = blockIdx.x * 32;
    int tid = threadIdx.x;
    int slot = tid >> 6;
    int b = tid & 63;
    float bias = g_imgb2[b];
    for (int rnd = 0; rnd < 8; rnd++) {
        int nl = rnd * 4 + slot;
        int n = n0 + nl;
        float acc = bias;
        int st = g_rowptr[n], en = g_rowptr[n + 1];
        for (int e = st; e < en; e++)
            acc += g_colw[e] * g_T2[(size_t)g_colsrc[e] * BBATCH + b];
        s[nl][b] = acc;
    }
    __syncthreads();
    #pragma unroll
    for (int i = 0; i < 8; i++) {
        int idx = tid + i * 256;
        int bb = idx >> 5, nn = idx & 31;
        out[(size_t)bb * NNODES + n0 + nn] = s[nn][bb];
    }
}

// ---------------- launch ----------------
extern "C" void kernel_launch(void* const* d_in, const int* in_sizes, int n_in,
                              void* d_out, int out_size) {
    const float* img  = (const float*)d_in[0];
    const float* nf   = (const float*)d_in[1];
    const int*   esrc = (const int*)d_in[2];
    const int*   edst = (const int*)d_in[3];
    const float* ew   = (const float*)d_in[4];
    const float* W1   = (const float*)d_in[5];
    const float* b1   = (const float*)d_in[6];
    const float* W2   = (const float*)d_in[7];
    const float* b2   = (const float*)d_in[8];
    float* out = (float*)d_out;

    float *dY, *dX1, *dW1t, *dT1, *dT2;
    cudaGetSymbolAddress((void**)&dY,   g_Y);
    cudaGetSymbolAddress((void**)&dX1,  g_X1);
    cudaGetSymbolAddress((void**)&dW1t, g_W1t);
    cudaGetSymbolAddress((void**)&dT1,  g_T1);
    cudaGetSymbolAddress((void**)&dT2,  g_T2);

    const int SMEM1 = 81920;   // gemm1: 2 stages x 40960
    const int SMEM2 = 61440;   // T2:    2 stages x 30720
    cudaFuncSetAttribute(k_gemm1, cudaFuncAttributeMaxDynamicSharedMemorySize, SMEM1);
    cudaFuncSetAttribute(mma_gemm<false, false>, cudaFuncAttributeMaxDynamicSharedMemorySize, SMEM2);

    // 0: zero scratch + transpose W1
    k_init<<<79 + 320, 256>>>(W1);
    // 1: degrees
    k_deg<<<(NEDGES + 255) / 256, 256>>>(edst, ew);
    // 2: scan + dinv
    k_scandinv<<<1, 1024>>>();
    // 3: CSR fill
    k_fill<<<(NEDGES + 255) / 256, 256>>>(esrc, edst, ew);
    // 4: layer-1 aggregation (width 300)
    k_aggY<<<NNODES, 128>>>(nf);
    // 5: X1 = leaky(Y @ W1 + b1), 128x128 tiles
    {
        dim3 grid(FHID / 128, (NNODES + 127) / 128);
        k_gemm1<<<grid, 512, SMEM1>>>(dY, dW1t, dX1, b1);
    }
    // 6: T1 partials (split-K SIMT fp32)
    {
        dim3 grid(FHID / 64, NSPLIT);
        k_t1_splitk<<<grid, 256>>>(img, W2);
    }
    // 7: reduce T1 + imgb2
    k_t1_reduce<<<257, 256>>>(img, b2);
    // 8: T2 = X1 @ T1^T
    {
        dim3 grid(1, (NNODES + 127) / 128);
        mma_gemm<false, false><<<grid, 256, SMEM2>>>(
            dX1, FHID, dT1, FHID, dT2, BBATCH, nullptr, NNODES, BBATCH, FHID);
    }
    // 9: output aggregation + fused transpose
    k_aggOutT<<<NNODES / 32, 256>>>(out);
}

// round 9
// speedup vs baseline: 1.1308x; 1.0723x over previous
#include <cuda_runtime.h>
#include <cuda_bf16.h>
#include <cstdint>

#define NNODES 20000
#define NEDGES 160000
#define BBATCH 64
#define FTEXT  300
#define FHID   1024
#define FOUT   1664
#define NEG_SLOPE 0.2f
#define NSPLIT 13          // T1 split-K factor (13 * 128 = 1664)
#define G1_GRID (16 * 157) // GEMM1 CTAs

// ---------------- scratch ----------------
__device__ float g_deg[NNODES];
__device__ float g_dinv[NNODES];
__device__ int   g_cnt[NNODES];
__device__ int   g_rowptr[NNODES + 1];
__device__ int   g_cursor[NNODES];
__device__ int   g_colsrc[NEDGES];
__device__ float g_colw[NEDGES];
__device__ float g_Y[(size_t)NNODES * FTEXT];
__device__ float g_X1[(size_t)NNODES * FHID];
__device__ float g_W1t[(size_t)FHID * FTEXT];
__device__ float g_T1p[(size_t)NSPLIT * BBATCH * FHID];
__device__ float g_T1[BBATCH * FHID];
__device__ float g_T2[(size_t)NNODES * BBATCH];
__device__ float g_imgb2[BBATCH];

// ---------------- PTX helpers (sm_80+ baseline only) ----------------
__device__ __forceinline__ uint32_t smem_to_u32(const void* p) {
    uint32_t a;
    asm("{ .reg .u64 t; cvta.to.shared.u64 t, %1; cvt.u32.u64 %0, t; }" : "=r"(a) : "l"(p));
    return a;
}
__device__ __forceinline__ void ldsm_x4(uint32_t* r, uint32_t addr) {
    asm volatile("ldmatrix.sync.aligned.m8n8.x4.shared.b16 {%0,%1,%2,%3}, [%4];"
        : "=r"(r[0]), "=r"(r[1]), "=r"(r[2]), "=r"(r[3]) : "r"(addr));
}
__device__ __forceinline__ void mma_bf16(float* c, const uint32_t* a, const uint32_t* b) {
    asm volatile(
        "mma.sync.aligned.m16n8k16.row.col.f32.bf16.bf16.f32 "
        "{%0,%1,%2,%3}, {%4,%5,%6,%7}, {%8,%9}, {%0,%1,%2,%3};"
        : "+f"(c[0]), "+f"(c[1]), "+f"(c[2]), "+f"(c[3])
        : "r"(a[0]), "r"(a[1]), "r"(a[2]), "r"(a[3]), "r"(b[0]), "r"(b[1]));
}
__device__ __forceinline__ void f4_hilo(float4 v, uint2& h, uint2& l) {
    __nv_bfloat16 hx = __float2bfloat16_rn(v.x);
    __nv_bfloat16 hy = __float2bfloat16_rn(v.y);
    __nv_bfloat16 hz = __float2bfloat16_rn(v.z);
    __nv_bfloat16 hw = __float2bfloat16_rn(v.w);
    __nv_bfloat16 lx = __float2bfloat16_rn(v.x - __bfloat162float(hx));
    __nv_bfloat16 ly = __float2bfloat16_rn(v.y - __bfloat162float(hy));
    __nv_bfloat16 lz = __float2bfloat16_rn(v.z - __bfloat162float(hz));
    __nv_bfloat16 lw = __float2bfloat16_rn(v.w - __bfloat162float(hw));
    __nv_bfloat162 h01(hx, hy), h23(hz, hw), l01(lx, ly), l23(lz, lw);
    h.x = *(uint32_t*)&h01; h.y = *(uint32_t*)&h23;
    l.x = *(uint32_t*)&l01; l.y = *(uint32_t*)&l23;
}

// ---------------- launch 0: zero scratch + transpose W1 (fp32) ---------------
__global__ void k_init(const float* __restrict__ W1) {
    const int ZBLK = 79;
    int tid = threadIdx.x;
    if (blockIdx.x < ZBLK) {
        int i = blockIdx.x * 256 + tid;
        if (i < NNODES) { g_deg[i] = 0.f; g_cnt[i] = 0; g_cursor[i] = 0; }
    } else {
        __shared__ float s[32][33];
        int bidx = blockIdx.x - ZBLK;
        int n0 = (bidx & 31) * 32;
        int k0 = (bidx >> 5) * 32;
        int tx = tid & 31, ty = tid >> 5;
        #pragma unroll
        for (int i = 0; i < 32; i += 8) {
            int k = k0 + ty + i, n = n0 + tx;
            if (k < FTEXT) s[ty + i][tx] = W1[(size_t)k * FHID + n];
        }
        __syncthreads();
        #pragma unroll
        for (int i = 0; i < 32; i += 8) {
            int n = n0 + ty + i, k = k0 + tx;
            if (k < FTEXT) g_W1t[(size_t)n * FTEXT + k] = s[tx][ty + i];
        }
    }
}

// ---------------- launch 1: degree ----------------
__global__ void k_deg(const int* __restrict__ dst, const float* __restrict__ w) {
    int e = blockIdx.x * blockDim.x + threadIdx.x;
    if (e < NEDGES) {
        int d = dst[e];
        atomicAdd(&g_deg[d], w[e]);
        atomicAdd(&g_cnt[d], 1);
    }
}

// ---------------- launch 2: warp-shuffle scan + dinv ----------------
__global__ void k_scandinv() {
    const int CH = 20;
    __shared__ int wtot[32];
    __shared__ int s_total;
    int t = threadIdx.x;
    int lane = t & 31, wid = t >> 5;
    int base = t * CH;
    int loc[CH];
    int sum = 0;
    #pragma unroll
    for (int i = 0; i < CH; i++) {
        int idx = base + i;
        int v = 0;
        if (idx < NNODES) {
            v = g_cnt[idx];
            float d = g_deg[idx];
            g_dinv[idx] = (d > 0.f) ? rsqrtf(d) : 0.f;
        }
        loc[i] = sum;
        sum += v;
    }
    int inc = sum;
    #pragma unroll
    for (int off = 1; off < 32; off <<= 1) {
        int v = __shfl_up_sync(0xffffffffu, inc, off);
        if (lane >= off) inc += v;
    }
    if (lane == 31) wtot[wid] = inc;
    __syncthreads();
    if (wid == 0) {
        int v = wtot[lane];
        int wi = v;
        #pragma unroll
        for (int off = 1; off < 32; off <<= 1) {
            int u = __shfl_up_sync(0xffffffffu, wi, off);
            if (lane >= off) wi += u;
        }
        wtot[lane] = wi - v;
        if (lane == 31) s_total = wi;
    }
    __syncthreads();
    int off0 = wtot[wid] + inc - sum;
    #pragma unroll
    for (int i = 0; i < CH; i++) {
        int idx = base + i;
        if (idx < NNODES) g_rowptr[idx] = off0 + loc[i];
    }
    if (t == 0) g_rowptr[NNODES] = s_total;
}

// ---------------- launch 3: fill CSR + T1 split-K (merged, both 256 thr) -----
// Blocks 0..624: CSR fill (atomic-latency-bound).
// Blocks 625..832: T1 partials (FMA-bound) — independent work, complementary pipes.
__global__ void __launch_bounds__(256) k_fill_t1(
    const int* __restrict__ src, const int* __restrict__ dst,
    const float* __restrict__ w,
    const float* __restrict__ img, const float* __restrict__ W2)
{
    __shared__ float As[16][64 + 1];
    __shared__ float Bs[16][64 + 1];
    int tid = threadIdx.x;
    if (blockIdx.x < 625) {
        int e = blockIdx.x * 256 + tid;
        if (e < NEDGES) {
            int s = src[e], d = dst[e];
            float nm = g_dinv[s] * w[e] * g_dinv[d];
            int pos = g_rowptr[d] + atomicAdd(&g_cursor[d], 1);
            g_colsrc[pos] = s;
            g_colw[pos]   = nm;
        }
    } else {
        // T1 partials: part[s][b][n] = sum_{k in s-th 128} img[b,k] * W2[n,k]
        int bidx = blockIdx.x - 625;          // 0..207
        int col0 = (bidx & 15) * 64;
        int sk = bidx >> 4;
        int kbase = sk * 128;
        const int BK = 16;
        int tx = tid & 15, ty = tid >> 4;
        float acc[4][4] = {};
        int r = tid >> 2, kq = (tid & 3) * 4;
        for (int t0 = 0; t0 < 128; t0 += BK) {
            float4 av = *(const float4*)(img + (size_t)r * FOUT + kbase + t0 + kq);
            As[kq + 0][r] = av.x; As[kq + 1][r] = av.y;
            As[kq + 2][r] = av.z; As[kq + 3][r] = av.w;
            float4 bv = *(const float4*)(W2 + (size_t)(col0 + r) * FOUT + kbase + t0 + kq);
            Bs[kq + 0][r] = bv.x; Bs[kq + 1][r] = bv.y;
            Bs[kq + 2][r] = bv.z; Bs[kq + 3][r] = bv.w;
            __syncthreads();
            #pragma unroll
            for (int k = 0; k < BK; k++) {
                float a[4], b[4];
                #pragma unroll
                for (int i = 0; i < 4; i++) a[i] = As[k][ty * 4 + i];
                #pragma unroll
                for (int j = 0; j < 4; j++) b[j] = Bs[k][tx * 4 + j];
                #pragma unroll
                for (int i = 0; i < 4; i++)
                    #pragma unroll
                    for (int j = 0; j < 4; j++)
                        acc[i][j] += a[i] * b[j];
            }
            __syncthreads();
        }
        float* cp = g_T1p + (size_t)sk * (BBATCH * FHID);
        #pragma unroll
        for (int i = 0; i < 4; i++) {
            int b = ty * 4 + i;
            #pragma unroll
            for (int j = 0; j < 4; j++)
                cp[(size_t)b * FHID + col0 + tx * 4 + j] = acc[i][j];
        }
    }
}

// ---------------- launch 4: Y = A @ X (width 300), R4 original ---------------
__global__ void k_aggY(const float* __restrict__ X) {
    __shared__ int   ss[128];
    __shared__ float sw[128];
    int n = blockIdx.x;
    int tid = threadIdx.x;
    int st = g_rowptr[n], en = g_rowptr[n + 1];
    float acc0 = 0.f, acc1 = 0.f, acc2 = 0.f;
    for (int e0 = st; e0 < en; e0 += 128) {
        int ne = min(128, en - e0);
        if (tid < ne) { ss[tid] = g_colsrc[e0 + tid]; sw[tid] = g_colw[e0 + tid]; }
        __syncthreads();
        for (int j = 0; j < ne; j++) {
            const float* xr = X + (size_t)ss[j] * FTEXT;
            float wv = sw[j];
            acc0 += wv * xr[tid];
            acc1 += wv * xr[tid + 128];
            if (tid + 256 < FTEXT) acc2 += wv * xr[tid + 256];
        }
        __syncthreads();
    }
    float* yr = g_Y + (size_t)n * FTEXT;
    yr[tid] = acc0;
    yr[tid + 128] = acc1;
    if (tid + 256 < FTEXT) yr[tid + 256] = acc2;
}

// ---------------- R4 GEMM core as device function (mechanical refactor) ------
// C[M,N] = A[M,K] @ B[N,K]^T ; bf16x3 in-STS split; CTA tile 128x64; BK=32.
template<bool BIAS, bool LEAKY>
__device__ __forceinline__ void gemm_core(
    const float* __restrict__ A, int lda,
    const float* __restrict__ B, int ldb,
    float* __restrict__ C, int ldc,
    const float* __restrict__ bias,
    int M, int N, int K, int bx, int by, char* smem)
{
    const int A_BYTES = 128 * 80;
    const int B_BYTES = 64 * 80;
    const int STAGE   = 2 * A_BYTES + 2 * B_BYTES;

    int tid  = threadIdx.x;
    int wid  = tid >> 5, lane = tid & 31;
    int wm   = wid & 3, wn = wid >> 2;
    int row0 = by * 128;
    int col0 = bx * 64;
    uint32_t smem_u = smem_to_u32(smem);

    float acc[2][4][4];
    #pragma unroll
    for (int mt = 0; mt < 2; mt++)
        #pragma unroll
        for (int nt = 0; nt < 4; nt++)
            #pragma unroll
            for (int q = 0; q < 4; q++) acc[mt][nt][q] = 0.f;

    float4 aR[4], bR[2];
    const int nT = (K + 31) >> 5;

    auto LDG = [&](int t) {
        int kb = t * 32;
        #pragma unroll
        for (int i = 0; i < 4; i++) {
            int idx = tid + i * 256;
            int r = idx >> 3, kk = (idx & 7) * 4;
            int row = row0 + r, kg = kb + kk;
            float4 v = make_float4(0.f, 0.f, 0.f, 0.f);
            if (row < M && kg < K) v = *(const float4*)(A + (size_t)row * lda + kg);
            aR[i] = v;
        }
        #pragma unroll
        for (int i = 0; i < 2; i++) {
            int idx = tid + i * 256;
            int c = idx >> 3, kk = (idx & 7) * 4;
            int col = col0 + c, kg = kb + kk;
            float4 v = make_float4(0.f, 0.f, 0.f, 0.f);
            if (col < N && kg < K) v = *(const float4*)(B + (size_t)col * ldb + kg);
            bR[i] = v;
        }
    };
    auto STS = [&](int s) {
        char* base = smem + s * STAGE;
        #pragma unroll
        for (int i = 0; i < 4; i++) {
            int idx = tid + i * 256;
            int r = idx >> 3, kk = (idx & 7) * 4;
            uint2 h, l;
            f4_hilo(aR[i], h, l);
            *(uint2*)(base + r * 80 + kk * 2) = h;
            *(uint2*)(base + A_BYTES + r * 80 + kk * 2) = l;
        }
        #pragma unroll
        for (int i = 0; i < 2; i++) {
            int idx = tid + i * 256;
            int c = idx >> 3, kk = (idx & 7) * 4;
            uint2 h, l;
            f4_hilo(bR[i], h, l);
            *(uint2*)(base + 2 * A_BYTES + c * 80 + kk * 2) = h;
            *(uint2*)(base + 2 * A_BYTES + B_BYTES + c * 80 + kk * 2) = l;
        }
    };
    auto COMPUTE = [&](int s) {
        uint32_t sb = smem_u + s * STAGE;
        uint32_t aH = sb + (uint32_t)((wm * 32 + (lane & 15)) * 80 + (lane >> 4) * 16);
        uint32_t aL = aH + A_BYTES;
        uint32_t bH = sb + 2 * A_BYTES +
            (uint32_t)((wn * 32 + ((lane >> 4) & 1) * 8 + (lane & 7)) * 80 + ((lane >> 3) & 1) * 16);
        uint32_t bL = bH + B_BYTES;
        #pragma unroll
        for (int ks = 0; ks < 2; ks++) {
            uint32_t ah[2][4], al[2][4], bh[2][4], bl[2][4];
            #pragma unroll
            for (int mt = 0; mt < 2; mt++) {
                ldsm_x4(ah[mt], aH + mt * 16 * 80 + ks * 32);
                ldsm_x4(al[mt], aL + mt * 16 * 80 + ks * 32);
            }
            #pragma unroll
            for (int g = 0; g < 2; g++) {
                ldsm_x4(bh[g], bH + g * 16 * 80 + ks * 32);
                ldsm_x4(bl[g], bL + g * 16 * 80 + ks * 32);
            }
            #pragma unroll
            for (int mt = 0; mt < 2; mt++)
                #pragma unroll
                for (int nt = 0; nt < 4; nt++) {
                    const uint32_t* ph = &bh[nt >> 1][(nt & 1) * 2];
                    const uint32_t* pl = &bl[nt >> 1][(nt & 1) * 2];
                    mma_bf16(acc[mt][nt], ah[mt], ph);
                    mma_bf16(acc[mt][nt], ah[mt], pl);
                    mma_bf16(acc[mt][nt], al[mt], ph);
                }
        }
    };

    LDG(0);
    STS(0);
    if (nT > 1) LDG(1);
    __syncthreads();
    for (int t = 0; t < nT; t++) {
        COMPUTE(t & 1);
        if (t + 1 < nT) STS((t + 1) & 1);
        __syncthreads();
        if (t + 2 < nT) LDG(t + 2);
    }

    int rw = row0 + wm * 32;
    int cw = col0 + wn * 32;
    #pragma unroll
    for (int mt = 0; mt < 2; mt++) {
        #pragma unroll
        for (int half = 0; half < 2; half++) {
            int row = rw + mt * 16 + (lane >> 2) + half * 8;
            if (row >= M) continue;
            #pragma unroll
            for (int nt = 0; nt < 4; nt++) {
                int col = cw + nt * 8 + (lane & 3) * 2;
                if (col >= N) continue;
                float v0 = acc[mt][nt][half * 2 + 0];
                float v1 = acc[mt][nt][half * 2 + 1];
                if (BIAS) { v0 += bias[col]; v1 += bias[col + 1]; }
                if (LEAKY) {
                    v0 = (v0 >= 0.f) ? v0 : NEG_SLOPE * v0;
                    v1 = (v1 >= 0.f) ? v1 : NEG_SLOPE * v1;
                }
                float2 o; o.x = v0; o.y = v1;
                *(float2*)(C + (size_t)row * ldc + col) = o;
            }
        }
    }
}

// ---------------- launch 5: GEMM1 + T1 reduce + imgb2 (merged) ---------------
__global__ void __launch_bounds__(256, 2) k_gemm1_fused(
    const float* __restrict__ A, const float* __restrict__ B,
    float* __restrict__ C, const float* __restrict__ bias,
    const float* __restrict__ img, const float* __restrict__ b2)
{
    extern __shared__ char smem[];
    if (blockIdx.x < G1_GRID) {
        int bx = blockIdx.x & 15;
        int by = blockIdx.x >> 4;
        gemm_core<true, true>(A, FTEXT, B, FTEXT, C, FHID, bias,
                              NNODES, FHID, FTEXT, bx, by, smem);
    } else if (blockIdx.x < G1_GRID + 256) {
        int idx = (blockIdx.x - G1_GRID) * 256 + threadIdx.x;   // 0..65535
        float acc = 0.f;
        #pragma unroll
        for (int s = 0; s < NSPLIT; s++)
            acc += g_T1p[(size_t)s * (BBATCH * FHID) + idx];
        g_T1[idx] = acc;
    } else {
        int wid = threadIdx.x >> 5, lane = threadIdx.x & 31;
        for (int i = 0; i < 8; i++) {
            int b = wid * 8 + i;
            float acc = 0.f;
            for (int k = lane; k < FOUT; k += 32)
                acc += img[(size_t)b * FOUT + k] * b2[k];
            #pragma unroll
            for (int off = 16; off > 0; off >>= 1)
                acc += __shfl_down_sync(0xffffffffu, acc, off);
            if (lane == 0) g_imgb2[b] = acc;
        }
    }
}

// ---------------- launch 6: T2 = X1 @ T1^T ----------------
__global__ void __launch_bounds__(256, 2) k_t2(
    const float* __restrict__ X1, const float* __restrict__ T1,
    float* __restrict__ T2)
{
    extern __shared__ char smem[];
    gemm_core<false, false>(X1, FHID, T1, FHID, T2, BBATCH, nullptr,
                            NNODES, BBATCH, FHID, 0, blockIdx.x, smem);
}

// ---------------- launch 7: output aggregation + fused transpose -------------
__global__ void __launch_bounds__(256) k_aggOutT(float* __restrict__ out) {
    __shared__ float s[32][65];
    int n0 = blockIdx.x * 32;
    int tid = threadIdx.x;
    int slot = tid >> 6;
    int b = tid & 63;
    float bias = g_imgb2[b];
    for (int rnd = 0; rnd < 8; rnd++) {
        int nl = rnd * 4 + slot;
        int n = n0 + nl;
        float acc = bias;
        int st = g_rowptr[n], en = g_rowptr[n + 1];
        for (int e = st; e < en; e++)
            acc += g_colw[e] * g_T2[(size_t)g_colsrc[e] * BBATCH + b];
        s[nl][b] = acc;
    }
    __syncthreads();
    #pragma unroll
    for (int i = 0; i < 8; i++) {
        int idx = tid + i * 256;
        int bb = idx >> 5, nn = idx & 31;
        out[(size_t)bb * NNODES + n0 + nn] = s[nn][bb];
    }
}

// ---------------- launch ----------------
extern "C" void kernel_launch(void* const* d_in, const int* in_sizes, int n_in,
                              void* d_out, int out_size) {
    const float* img  = (const float*)d_in[0];
    const float* nf   = (const float*)d_in[1];
    const int*   esrc = (const int*)d_in[2];
    const int*   edst = (const int*)d_in[3];
    const float* ew   = (const float*)d_in[4];
    const float* W1   = (const float*)d_in[5];
    const float* b1   = (const float*)d_in[6];
    const float* W2   = (const float*)d_in[7];
    const float* b2   = (const float*)d_in[8];
    float* out = (float*)d_out;

    float *dY, *dX1, *dW1t, *dT1, *dT2;
    cudaGetSymbolAddress((void**)&dY,   g_Y);
    cudaGetSymbolAddress((void**)&dX1,  g_X1);
    cudaGetSymbolAddress((void**)&dW1t, g_W1t);
    cudaGetSymbolAddress((void**)&dT1,  g_T1);
    cudaGetSymbolAddress((void**)&dT2,  g_T2);

    const int SMEM = 61440;  // 2 stages x 30720
    cudaFuncSetAttribute(k_gemm1_fused, cudaFuncAttributeMaxDynamicSharedMemorySize, SMEM);
    cudaFuncSetAttribute(k_t2,          cudaFuncAttributeMaxDynamicSharedMemorySize, SMEM);

    // 0: zero scratch + transpose W1
    k_init<<<79 + 320, 256>>>(W1);
    // 1: degrees
    k_deg<<<(NEDGES + 255) / 256, 256>>>(edst, ew);
    // 2: scan + dinv
    k_scandinv<<<1, 1024>>>();
    // 3: CSR fill + T1 split-K (merged; independent, complementary pipes)
    k_fill_t1<<<625 + 16 * NSPLIT, 256>>>(esrc, edst, ew, img, W2);
    // 4: layer-1 aggregation (width 300)
    k_aggY<<<NNODES, 128>>>(nf);
    // 5: GEMM1 + T1 reduce + imgb2 (merged)
    k_gemm1_fused<<<G1_GRID + 256 + 1, 256, SMEM>>>(dY, dW1t, dX1, b1, img, b2);
    // 6: T2 = X1 @ T1^T
    k_t2<<<157, 256, SMEM>>>(dX1, dT1, dT2);
    // 7: output aggregation + fused transpose
    k_aggOutT<<<NNODES / 32, 256>>>(out);
}

// round 10
// speedup vs baseline: 1.1504x; 1.0174x over previous
#include <cuda_runtime.h>
#include <cuda_bf16.h>
#include <cstdint>

#define NNODES 20000
#define NEDGES 160000
#define BBATCH 64
#define FTEXT  300
#define FHID   1024
#define FOUT   1664
#define NEG_SLOPE 0.2f
#define NSPLIT 13          // T1 split-K factor (13 * 128 = 1664)
#define G1_GRID (16 * 157) // GEMM1 CTAs

// ---------------- scratch (zero-initialized at load; re-zeroed each run) -----
__device__ float g_deg[NNODES];
__device__ float g_dinv[NNODES];
__device__ int   g_cnt[NNODES];
__device__ int   g_rowptr[NNODES + 1];
__device__ int   g_cursor[NNODES];
__device__ int   g_colsrc[NEDGES];
__device__ float g_colw[NEDGES];
__device__ float g_Y[(size_t)NNODES * FTEXT];
__device__ float g_X1[(size_t)NNODES * FHID];
__device__ float g_W1t[(size_t)FHID * FTEXT];
__device__ float g_T1p[(size_t)NSPLIT * BBATCH * FHID];
__device__ float g_T1[BBATCH * FHID];
__device__ float g_T2[(size_t)NNODES * BBATCH];
__device__ float g_imgb2[BBATCH];

// ---------------- PTX helpers (sm_80+ baseline only) ----------------
__device__ __forceinline__ uint32_t smem_to_u32(const void* p) {
    uint32_t a;
    asm("{ .reg .u64 t; cvta.to.shared.u64 t, %1; cvt.u32.u64 %0, t; }" : "=r"(a) : "l"(p));
    return a;
}
__device__ __forceinline__ void ldsm_x4(uint32_t* r, uint32_t addr) {
    asm volatile("ldmatrix.sync.aligned.m8n8.x4.shared.b16 {%0,%1,%2,%3}, [%4];"
        : "=r"(r[0]), "=r"(r[1]), "=r"(r[2]), "=r"(r[3]) : "r"(addr));
}
__device__ __forceinline__ void mma_bf16(float* c, const uint32_t* a, const uint32_t* b) {
    asm volatile(
        "mma.sync.aligned.m16n8k16.row.col.f32.bf16.bf16.f32 "
        "{%0,%1,%2,%3}, {%4,%5,%6,%7}, {%8,%9}, {%0,%1,%2,%3};"
        : "+f"(c[0]), "+f"(c[1]), "+f"(c[2]), "+f"(c[3])
        : "r"(a[0]), "r"(a[1]), "r"(a[2]), "r"(a[3]), "r"(b[0]), "r"(b[1]));
}
__device__ __forceinline__ void f4_hilo(float4 v, uint2& h, uint2& l) {
    __nv_bfloat16 hx = __float2bfloat16_rn(v.x);
    __nv_bfloat16 hy = __float2bfloat16_rn(v.y);
    __nv_bfloat16 hz = __float2bfloat16_rn(v.z);
    __nv_bfloat16 hw = __float2bfloat16_rn(v.w);
    __nv_bfloat16 lx = __float2bfloat16_rn(v.x - __bfloat162float(hx));
    __nv_bfloat16 ly = __float2bfloat16_rn(v.y - __bfloat162float(hy));
    __nv_bfloat16 lz = __float2bfloat16_rn(v.z - __bfloat162float(hz));
    __nv_bfloat16 lw = __float2bfloat16_rn(v.w - __bfloat162float(hw));
    __nv_bfloat162 h01(hx, hy), h23(hz, hw), l01(lx, ly), l23(lz, lw);
    h.x = *(uint32_t*)&h01; h.y = *(uint32_t*)&h23;
    l.x = *(uint32_t*)&l01; l.y = *(uint32_t*)&l23;
}

// ---------------- launch 0: degree atomics + W1 transpose (independent) ------
__global__ void k_deg_w1t(const int* __restrict__ dst, const float* __restrict__ w,
                          const float* __restrict__ W1) {
    int tid = threadIdx.x;
    if (blockIdx.x < 625) {
        int e = blockIdx.x * 256 + tid;
        if (e < NEDGES) {
            int d = dst[e];
            atomicAdd(&g_deg[d], w[e]);
            atomicAdd(&g_cnt[d], 1);
        }
    } else {
        __shared__ float s[32][33];
        int bidx = blockIdx.x - 625;           // 0..319 (32 n-tiles x 10 k-tiles)
        int n0 = (bidx & 31) * 32;
        int k0 = (bidx >> 5) * 32;
        int tx = tid & 31, ty = tid >> 5;
        #pragma unroll
        for (int i = 0; i < 32; i += 8) {
            int k = k0 + ty + i, n = n0 + tx;
            if (k < FTEXT) s[ty + i][tx] = W1[(size_t)k * FHID + n];
        }
        __syncthreads();
        #pragma unroll
        for (int i = 0; i < 32; i += 8) {
            int n = n0 + ty + i, k = k0 + tx;
            if (k < FTEXT) g_W1t[(size_t)n * FTEXT + k] = s[tx][ty + i];
        }
    }
}

// ---------------- launch 1: warp-shuffle scan + dinv ----------------
__global__ void k_scandinv() {
    const int CH = 20;
    __shared__ int wtot[32];
    __shared__ int s_total;
    int t = threadIdx.x;
    int lane = t & 31, wid = t >> 5;
    int base = t * CH;
    int loc[CH];
    int sum = 0;
    #pragma unroll
    for (int i = 0; i < CH; i++) {
        int idx = base + i;
        int v = 0;
        if (idx < NNODES) {
            v = g_cnt[idx];
            float d = g_deg[idx];
            g_dinv[idx] = (d > 0.f) ? rsqrtf(d) : 0.f;
        }
        loc[i] = sum;
        sum += v;
    }
    int inc = sum;
    #pragma unroll
    for (int off = 1; off < 32; off <<= 1) {
        int v = __shfl_up_sync(0xffffffffu, inc, off);
        if (lane >= off) inc += v;
    }
    if (lane == 31) wtot[wid] = inc;
    __syncthreads();
    if (wid == 0) {
        int v = wtot[lane];
        int wi = v;
        #pragma unroll
        for (int off = 1; off < 32; off <<= 1) {
            int u = __shfl_up_sync(0xffffffffu, wi, off);
            if (lane >= off) wi += u;
        }
        wtot[lane] = wi - v;
        if (lane == 31) s_total = wi;
    }
    __syncthreads();
    int off0 = wtot[wid] + inc - sum;
    #pragma unroll
    for (int i = 0; i < CH; i++) {
        int idx = base + i;
        if (idx < NNODES) g_rowptr[idx] = off0 + loc[i];
    }
    if (t == 0) g_rowptr[NNODES] = s_total;
}

// ---------------- launch 2: fill CSR + T1 split-K (merged) ----------------
__global__ void __launch_bounds__(256) k_fill_t1(
    const int* __restrict__ src, const int* __restrict__ dst,
    const float* __restrict__ w,
    const float* __restrict__ img, const float* __restrict__ W2)
{
    __shared__ float As[16][64 + 1];
    __shared__ float Bs[16][64 + 1];
    int tid = threadIdx.x;
    if (blockIdx.x < 625) {
        int e = blockIdx.x * 256 + tid;
        if (e < NEDGES) {
            int s = src[e], d = dst[e];
            float nm = g_dinv[s] * w[e] * g_dinv[d];
            int pos = g_rowptr[d] + atomicAdd(&g_cursor[d], 1);
            g_colsrc[pos] = s;
            g_colw[pos]   = nm;
        }
    } else {
        int bidx = blockIdx.x - 625;          // 0..207
        int col0 = (bidx & 15) * 64;
        int sk = bidx >> 4;
        int kbase = sk * 128;
        const int BK = 16;
        int tx = tid & 15, ty = tid >> 4;
        float acc[4][4] = {};
        int r = tid >> 2, kq = (tid & 3) * 4;
        for (int t0 = 0; t0 < 128; t0 += BK) {
            float4 av = *(const float4*)(img + (size_t)r * FOUT + kbase + t0 + kq);
            As[kq + 0][r] = av.x; As[kq + 1][r] = av.y;
            As[kq + 2][r] = av.z; As[kq + 3][r] = av.w;
            float4 bv = *(const float4*)(W2 + (size_t)(col0 + r) * FOUT + kbase + t0 + kq);
            Bs[kq + 0][r] = bv.x; Bs[kq + 1][r] = bv.y;
            Bs[kq + 2][r] = bv.z; Bs[kq + 3][r] = bv.w;
            __syncthreads();
            #pragma unroll
            for (int k = 0; k < BK; k++) {
                float a[4], b[4];
                #pragma unroll
                for (int i = 0; i < 4; i++) a[i] = As[k][ty * 4 + i];
                #pragma unroll
                for (int j = 0; j < 4; j++) b[j] = Bs[k][tx * 4 + j];
                #pragma unroll
                for (int i = 0; i < 4; i++)
                    #pragma unroll
                    for (int j = 0; j < 4; j++)
                        acc[i][j] += a[i] * b[j];
            }
            __syncthreads();
        }
        float* cp = g_T1p + (size_t)sk * (BBATCH * FHID);
        #pragma unroll
        for (int i = 0; i < 4; i++) {
            int b = ty * 4 + i;
            #pragma unroll
            for (int j = 0; j < 4; j++)
                cp[(size_t)b * FHID + col0 + tx * 4 + j] = acc[i][j];
        }
    }
}

// ---------------- launch 3: Y = A @ X (width 300), unroll x2 -----------------
__global__ void k_aggY(const float* __restrict__ X) {
    __shared__ int   ss[128];
    __shared__ float sw[128];
    int n = blockIdx.x;
    int tid = threadIdx.x;
    int st = g_rowptr[n], en = g_rowptr[n + 1];
    float acc0 = 0.f, acc1 = 0.f, acc2 = 0.f;
    bool has2 = (tid + 256 < FTEXT);
    for (int e0 = st; e0 < en; e0 += 128) {
        int ne = min(128, en - e0);
        if (tid < ne) { ss[tid] = g_colsrc[e0 + tid]; sw[tid] = g_colw[e0 + tid]; }
        __syncthreads();
        int j = 0;
        for (; j + 2 <= ne; j += 2) {
            const float* x0 = X + (size_t)ss[j] * FTEXT;
            const float* x1 = X + (size_t)ss[j + 1] * FTEXT;
            float w0 = sw[j], w1 = sw[j + 1];
            float p0 = x0[tid], q0 = x1[tid];
            float p1 = x0[tid + 128], q1 = x1[tid + 128];
            float p2 = 0.f, q2 = 0.f;
            if (has2) { p2 = x0[tid + 256]; q2 = x1[tid + 256]; }
            acc0 += w0 * p0; acc1 += w0 * p1; acc2 += w0 * p2;
            acc0 += w1 * q0; acc1 += w1 * q1; acc2 += w1 * q2;
        }
        if (j < ne) {
            const float* x0 = X + (size_t)ss[j] * FTEXT;
            float w0 = sw[j];
            acc0 += w0 * x0[tid];
            acc1 += w0 * x0[tid + 128];
            if (has2) acc2 += w0 * x0[tid + 256];
        }
        __syncthreads();
    }
    float* yr = g_Y + (size_t)n * FTEXT;
    yr[tid] = acc0;
    yr[tid + 128] = acc1;
    if (has2) yr[tid + 256] = acc2;
}

// ---------------- R4 GEMM core, 128x64 CTA tile, 256 threads -----------------
template<bool BIAS, bool LEAKY>
__device__ __forceinline__ void gemm_core(
    const float* __restrict__ A, int lda,
    const float* __restrict__ B, int ldb,
    float* __restrict__ C, int ldc,
    const float* __restrict__ bias,
    int M, int N, int K, int bx, int by, char* smem)
{
    const int A_BYTES = 128 * 80;
    const int B_BYTES = 64 * 80;
    const int STAGE   = 2 * A_BYTES + 2 * B_BYTES;

    int tid  = threadIdx.x;
    int wid  = tid >> 5, lane = tid & 31;
    int wm   = wid & 3, wn = wid >> 2;
    int row0 = by * 128;
    int col0 = bx * 64;
    uint32_t smem_u = smem_to_u32(smem);

    float acc[2][4][4];
    #pragma unroll
    for (int mt = 0; mt < 2; mt++)
        #pragma unroll
        for (int nt = 0; nt < 4; nt++)
            #pragma unroll
            for (int q = 0; q < 4; q++) acc[mt][nt][q] = 0.f;

    float4 aR[4], bR[2];
    const int nT = (K + 31) >> 5;

    auto LDG = [&](int t) {
        int kb = t * 32;
        #pragma unroll
        for (int i = 0; i < 4; i++) {
            int idx = tid + i * 256;
            int r = idx >> 3, kk = (idx & 7) * 4;
            int row = row0 + r, kg = kb + kk;
            float4 v = make_float4(0.f, 0.f, 0.f, 0.f);
            if (row < M && kg < K) v = *(const float4*)(A + (size_t)row * lda + kg);
            aR[i] = v;
        }
        #pragma unroll
        for (int i = 0; i < 2; i++) {
            int idx = tid + i * 256;
            int c = idx >> 3, kk = (idx & 7) * 4;
            int col = col0 + c, kg = kb + kk;
            float4 v = make_float4(0.f, 0.f, 0.f, 0.f);
            if (col < N && kg < K) v = *(const float4*)(B + (size_t)col * ldb + kg);
            bR[i] = v;
        }
    };
    auto STS = [&](int s) {
        char* base = smem + s * STAGE;
        #pragma unroll
        for (int i = 0; i < 4; i++) {
            int idx = tid + i * 256;
            int r = idx >> 3, kk = (idx & 7) * 4;
            uint2 h, l;
            f4_hilo(aR[i], h, l);
            *(uint2*)(base + r * 80 + kk * 2) = h;
            *(uint2*)(base + A_BYTES + r * 80 + kk * 2) = l;
        }
        #pragma unroll
        for (int i = 0; i < 2; i++) {
            int idx = tid + i * 256;
            int c = idx >> 3, kk = (idx & 7) * 4;
            uint2 h, l;
            f4_hilo(bR[i], h, l);
            *(uint2*)(base + 2 * A_BYTES + c * 80 + kk * 2) = h;
            *(uint2*)(base + 2 * A_BYTES + B_BYTES + c * 80 + kk * 2) = l;
        }
    };
    auto COMPUTE = [&](int s) {
        uint32_t sb = smem_u + s * STAGE;
        uint32_t aH = sb + (uint32_t)((wm * 32 + (lane & 15)) * 80 + (lane >> 4) * 16);
        uint32_t aL = aH + A_BYTES;
        uint32_t bH = sb + 2 * A_BYTES +
            (uint32_t)((wn * 32 + ((lane >> 4) & 1) * 8 + (lane & 7)) * 80 + ((lane >> 3) & 1) * 16);
        uint32_t bL = bH + B_BYTES;
        #pragma unroll
        for (int ks = 0; ks < 2; ks++) {
            uint32_t ah[2][4], al[2][4], bh[2][4], bl[2][4];
            #pragma unroll
            for (int mt = 0; mt < 2; mt++) {
                ldsm_x4(ah[mt], aH + mt * 16 * 80 + ks * 32);
                ldsm_x4(al[mt], aL + mt * 16 * 80 + ks * 32);
            }
            #pragma unroll
            for (int g = 0; g < 2; g++) {
                ldsm_x4(bh[g], bH + g * 16 * 80 + ks * 32);
                ldsm_x4(bl[g], bL + g * 16 * 80 + ks * 32);
            }
            #pragma unroll
            for (int mt = 0; mt < 2; mt++)
                #pragma unroll
                for (int nt = 0; nt < 4; nt++) {
                    const uint32_t* ph = &bh[nt >> 1][(nt & 1) * 2];
                    const uint32_t* pl = &bl[nt >> 1][(nt & 1) * 2];
                    mma_bf16(acc[mt][nt], ah[mt], ph);
                    mma_bf16(acc[mt][nt], ah[mt], pl);
                    mma_bf16(acc[mt][nt], al[mt], ph);
                }
        }
    };

    LDG(0);
    STS(0);
    if (nT > 1) LDG(1);
    __syncthreads();
    for (int t = 0; t < nT; t++) {
        COMPUTE(t & 1);
        if (t + 1 < nT) STS((t + 1) & 1);
        __syncthreads();
        if (t + 2 < nT) LDG(t + 2);
    }

    int rw = row0 + wm * 32;
    int cw = col0 + wn * 32;
    #pragma unroll
    for (int mt = 0; mt < 2; mt++) {
        #pragma unroll
        for (int half = 0; half < 2; half++) {
            int row = rw + mt * 16 + (lane >> 2) + half * 8;
            if (row >= M) continue;
            #pragma unroll
            for (int nt = 0; nt < 4; nt++) {
                int col = cw + nt * 8 + (lane & 3) * 2;
                if (col >= N) continue;
                float v0 = acc[mt][nt][half * 2 + 0];
                float v1 = acc[mt][nt][half * 2 + 1];
                if (BIAS) { v0 += bias[col]; v1 += bias[col + 1]; }
                if (LEAKY) {
                    v0 = (v0 >= 0.f) ? v0 : NEG_SLOPE * v0;
                    v1 = (v1 >= 0.f) ? v1 : NEG_SLOPE * v1;
                }
                float2 o; o.x = v0; o.y = v1;
                *(float2*)(C + (size_t)row * ldc + col) = o;
            }
        }
    }
}

// ---------------- launch 4: GEMM1 + T1 reduce + imgb2 (merged) ---------------
__global__ void __launch_bounds__(256, 2) k_gemm1_fused(
    const float* __restrict__ A, const float* __restrict__ B,
    float* __restrict__ C, const float* __restrict__ bias,
    const float* __restrict__ img, const float* __restrict__ b2)
{
    extern __shared__ char smem[];
    if (blockIdx.x < G1_GRID) {
        int bx = blockIdx.x & 15;
        int by = blockIdx.x >> 4;
        gemm_core<true, true>(A, FTEXT, B, FTEXT, C, FHID, bias,
                              NNODES, FHID, FTEXT, bx, by, smem);
    } else if (blockIdx.x < G1_GRID + 256) {
        int idx = (blockIdx.x - G1_GRID) * 256 + threadIdx.x;
        float acc = 0.f;
        #pragma unroll
        for (int s = 0; s < NSPLIT; s++)
            acc += g_T1p[(size_t)s * (BBATCH * FHID) + idx];
        g_T1[idx] = acc;
    } else {
        int wid = threadIdx.x >> 5, lane = threadIdx.x & 31;
        for (int i = 0; i < 8; i++) {
            int b = wid * 8 + i;
            float acc = 0.f;
            for (int k = lane; k < FOUT; k += 32)
                acc += img[(size_t)b * FOUT + k] * b2[k];
            #pragma unroll
            for (int off = 16; off > 0; off >>= 1)
                acc += __shfl_down_sync(0xffffffffu, acc, off);
            if (lane == 0) g_imgb2[b] = acc;
        }
    }
}

// ---------------- launch 5: T2 = X1 @ T1^T, 64-row tiles (load-balanced) -----
// 128 threads, 4 warps in 2x2; 313 CTAs; warp tile 32x32 identical to gemm_core.
__global__ void __launch_bounds__(128, 4) k_t2(
    const float* __restrict__ A, const float* __restrict__ B,
    float* __restrict__ C)
{
    extern __shared__ char smem[];
    const int A64 = 64 * 80;
    const int B64 = 64 * 80;
    const int STAGE = 2 * A64 + 2 * B64;   // 20480
    const int M = NNODES, K = FHID;

    int tid = threadIdx.x;
    int wid = tid >> 5, lane = tid & 31;
    int wm = wid & 1, wn = wid >> 1;       // 2x2 warps, 32x32 each
    int row0 = blockIdx.x * 64;
    uint32_t smem_u = smem_to_u32(smem);

    float acc[2][4][4];
    #pragma unroll
    for (int mt = 0; mt < 2; mt++)
        #pragma unroll
        for (int nt = 0; nt < 4; nt++)
            #pragma unroll
            for (int q = 0; q < 4; q++) acc[mt][nt][q] = 0.f;

    float4 aR[4], bR[4];
    const int nT = K >> 5;                 // 32

    auto LDG = [&](int t) {
        int kb = t * 32;
        #pragma unroll
        for (int i = 0; i < 4; i++) {
            int idx = tid + i * 128;       // 0..511
            int r = idx >> 3, kk = (idx & 7) * 4;
            int row = row0 + r; row = (row < M) ? row : (M - 1);
            aR[i] = *(const float4*)(A + (size_t)row * K + kb + kk);
            bR[i] = *(const float4*)(B + (size_t)r * K + kb + kk);
        }
    };
    auto STS = [&](int s) {
        char* base = smem + s * STAGE;
        #pragma unroll
        for (int i = 0; i < 4; i++) {
            int idx = tid + i * 128;
            int r = idx >> 3, kk = (idx & 7) * 4;
            uint2 h, l;
            f4_hilo(aR[i], h, l);
            *(uint2*)(base + r * 80 + kk * 2) = h;
            *(uint2*)(base + A64 + r * 80 + kk * 2) = l;
            f4_hilo(bR[i], h, l);
            *(uint2*)(base + 2 * A64 + r * 80 + kk * 2) = h;
            *(uint2*)(base + 2 * A64 + B64 + r * 80 + kk * 2) = l;
        }
    };
    auto COMPUTE = [&](int s) {
        uint32_t sb = smem_u + s * STAGE;
        uint32_t aH = sb + (uint32_t)((wm * 32 + (lane & 15)) * 80 + (lane >> 4) * 16);
        uint32_t aL = aH + A64;
        uint32_t bH = sb + 2 * A64 +
            (uint32_t)((wn * 32 + ((lane >> 4) & 1) * 8 + (lane & 7)) * 80 + ((lane >> 3) & 1) * 16);
        uint32_t bL = bH + B64;
        #pragma unroll
        for (int ks = 0; ks < 2; ks++) {
            uint32_t ah[2][4], al[2][4], bh[2][4], bl[2][4];
            #pragma unroll
            for (int mt = 0; mt < 2; mt++) {
                ldsm_x4(ah[mt], aH + mt * 16 * 80 + ks * 32);
                ldsm_x4(al[mt], aL + mt * 16 * 80 + ks * 32);
            }
            #pragma unroll
            for (int g = 0; g < 2; g++) {
                ldsm_x4(bh[g], bH + g * 16 * 80 + ks * 32);
                ldsm_x4(bl[g], bL + g * 16 * 80 + ks * 32);
            }
            #pragma unroll
            for (int mt = 0; mt < 2; mt++)
                #pragma unroll
                for (int nt = 0; nt < 4; nt++) {
                    const uint32_t* ph = &bh[nt >> 1][(nt & 1) * 2];
                    const uint32_t* pl = &bl[nt >> 1][(nt & 1) * 2];
                    mma_bf16(acc[mt][nt], ah[mt], ph);
                    mma_bf16(acc[mt][nt], ah[mt], pl);
                    mma_bf16(acc[mt][nt], al[mt], ph);
                }
        }
    };

    LDG(0);
    STS(0);
    LDG(1);
    __syncthreads();
    for (int t = 0; t < nT; t++) {
        COMPUTE(t & 1);
        if (t + 1 < nT) STS((t + 1) & 1);
        __syncthreads();
        if (t + 2 < nT) LDG(t + 2);
    }

    int rw = row0 + wm * 32;
    int cw = wn * 32;
    #pragma unroll
    for (int mt = 0; mt < 2; mt++) {
        #pragma unroll
        for (int half = 0; half < 2; half++) {
            int row = rw + mt * 16 + (lane >> 2) + half * 8;
            if (row >= M) continue;
            #pragma unroll
            for (int nt = 0; nt < 4; nt++) {
                int col = cw + nt * 8 + (lane & 3) * 2;
                float2 o;
                o.x = acc[mt][nt][half * 2 + 0];
                o.y = acc[mt][nt][half * 2 + 1];
                *(float2*)(C + (size_t)row * BBATCH + col) = o;
            }
        }
    }
}

// ---------------- launch 6: output agg + transpose + re-zero scratch ---------
__global__ void __launch_bounds__(256) k_aggOutT(float* __restrict__ out) {
    if (blockIdx.x >= 625) {
        // re-zero scratch for the next graph replay (statics are zero on call 1)
        int i = (blockIdx.x - 625) * 256 + threadIdx.x;
        if (i < NNODES) { g_deg[i] = 0.f; g_cnt[i] = 0; g_cursor[i] = 0; }
        return;
    }
    __shared__ float s[32][65];
    int n0 = blockIdx.x * 32;
    int tid = threadIdx.x;
    int slot = tid >> 6;
    int b = tid & 63;
    float bias = g_imgb2[b];
    for (int rnd = 0; rnd < 8; rnd++) {
        int nl = rnd * 4 + slot;
        int n = n0 + nl;
        float acc = bias;
        int st = g_rowptr[n], en = g_rowptr[n + 1];
        for (int e = st; e < en; e++)
            acc += g_colw[e] * g_T2[(size_t)g_colsrc[e] * BBATCH + b];
        s[nl][b] = acc;
    }
    __syncthreads();
    #pragma unroll
    for (int i = 0; i < 8; i++) {
        int idx = tid + i * 256;
        int bb = idx >> 5, nn = idx & 31;
        out[(size_t)bb * NNODES + n0 + nn] = s[nn][bb];
    }
}

// ---------------- launch ----------------
extern "C" void kernel_launch(void* const* d_in, const int* in_sizes, int n_in,
                              void* d_out, int out_size) {
    const float* img  = (const float*)d_in[0];
    const float* nf   = (const float*)d_in[1];
    const int*   esrc = (const int*)d_in[2];
    const int*   edst = (const int*)d_in[3];
    const float* ew   = (const float*)d_in[4];
    const float* W1   = (const float*)d_in[5];
    const float* b1   = (const float*)d_in[6];
    const float* W2   = (const float*)d_in[7];
    const float* b2   = (const float*)d_in[8];
    float* out = (float*)d_out;

    float *dY, *dX1, *dW1t, *dT1, *dT2;
    cudaGetSymbolAddress((void**)&dY,   g_Y);
    cudaGetSymbolAddress((void**)&dX1,  g_X1);
    cudaGetSymbolAddress((void**)&dW1t, g_W1t);
    cudaGetSymbolAddress((void**)&dT1,  g_T1);
    cudaGetSymbolAddress((void**)&dT2,  g_T2);

    const int SMEM1 = 61440;   // gemm_core: 2 stages x 30720
    const int SMEM2 = 40960;   // k_t2:      2 stages x 20480
    cudaFuncSetAttribute(k_gemm1_fused, cudaFuncAttributeMaxDynamicSharedMemorySize, SMEM1);
    cudaFuncSetAttribute(k_t2,          cudaFuncAttributeMaxDynamicSharedMemorySize, SMEM2);

    // 0: degree atomics + W1 transpose (scratch pre-zeroed by previous run)
    k_deg_w1t<<<625 + 320, 256>>>(edst, ew, W1);
    // 1: scan + dinv
    k_scandinv<<<1, 1024>>>();
    // 2: CSR fill + T1 split-K
    k_fill_t1<<<625 + 16 * NSPLIT, 256>>>(esrc, edst, ew, img, W2);
    // 3: layer-1 aggregation
    k_aggY<<<NNODES, 128>>>(nf);
    // 4: GEMM1 + T1 reduce + imgb2
    k_gemm1_fused<<<G1_GRID + 256 + 1, 256, SMEM1>>>(dY, dW1t, dX1, b1, img, b2);
    // 5: T2 (64-row tiles, 313 CTAs)
    k_t2<<<(NNODES + 63) / 64, 128, SMEM2>>>(dX1, dT1, dT2);
    // 6: output aggregation + transpose + re-zero scratch
    k_aggOutT<<<625 + 79, 256>>>(out);
}

// round 11
// speedup vs baseline: 1.2663x; 1.1007x over previous
#include <cuda_runtime.h>
#include <cuda_fp16.h>
#include <cstdint>

#define NNODES 20000
#define NEDGES 160000
#define BBATCH 64
#define FTEXT  300
#define FHID   1024
#define FOUT   1664
#define NEG_SLOPE 0.2f
#define NSPLIT 13          // T1 split-K factor (13 * 128 = 1664)
#define G1_GRID (16 * 157) // GEMM1 CTAs

// ---------------- scratch (zero-initialized at load; re-zeroed each run) -----
__device__ float g_deg[NNODES];
__device__ float g_dinv[NNODES];
__device__ int   g_cnt[NNODES];
__device__ int   g_rowptr[NNODES + 1];
__device__ int   g_cursor[NNODES];
__device__ int   g_colsrc[NEDGES];
__device__ float g_colw[NEDGES];
__device__ float g_Y[(size_t)NNODES * FTEXT];
__device__ float g_X1[(size_t)NNODES * FHID];
__device__ float g_W1t[(size_t)FHID * FTEXT];
__device__ float g_T1p[(size_t)NSPLIT * BBATCH * FHID];
__device__ float g_T1[BBATCH * FHID];
__device__ float g_T2[(size_t)NNODES * BBATCH];
__device__ float g_imgb2[BBATCH];

// ---------------- PTX helpers (sm_80+ baseline only) ----------------
__device__ __forceinline__ uint32_t smem_to_u32(const void* p) {
    uint32_t a;
    asm("{ .reg .u64 t; cvta.to.shared.u64 t, %1; cvt.u32.u64 %0, t; }" : "=r"(a) : "l"(p));
    return a;
}
__device__ __forceinline__ void ldsm_x4(uint32_t* r, uint32_t addr) {
    asm volatile("ldmatrix.sync.aligned.m8n8.x4.shared.b16 {%0,%1,%2,%3}, [%4];"
        : "=r"(r[0]), "=r"(r[1]), "=r"(r[2]), "=r"(r[3]) : "r"(addr));
}
__device__ __forceinline__ void mma_f16(float* c, const uint32_t* a, const uint32_t* b) {
    asm volatile(
        "mma.sync.aligned.m16n8k16.row.col.f32.f16.f16.f32 "
        "{%0,%1,%2,%3}, {%4,%5,%6,%7}, {%8,%9}, {%0,%1,%2,%3};"
        : "+f"(c[0]), "+f"(c[1]), "+f"(c[2]), "+f"(c[3])
        : "r"(a[0]), "r"(a[1]), "r"(a[2]), "r"(a[3]), "r"(b[0]), "r"(b[1]));
}
// fp16 split of float4: h = rn(v), l = rn(v - h)   (~22-bit combined mantissa)
__device__ __forceinline__ void f4_hilo_h(float4 v, uint2& h, uint2& l) {
    __half hx = __float2half_rn(v.x);
    __half hy = __float2half_rn(v.y);
    __half hz = __float2half_rn(v.z);
    __half hw = __float2half_rn(v.w);
    __half lx = __float2half_rn(v.x - __half2float(hx));
    __half ly = __float2half_rn(v.y - __half2float(hy));
    __half lz = __float2half_rn(v.z - __half2float(hz));
    __half lw = __float2half_rn(v.w - __half2float(hw));
    __half2 h01(hx, hy), h23(hz, hw), l01(lx, ly), l23(lz, lw);
    h.x = *(uint32_t*)&h01; h.y = *(uint32_t*)&h23;
    l.x = *(uint32_t*)&l01; l.y = *(uint32_t*)&l23;
}
// fp16 round-only (for B operand)
__device__ __forceinline__ uint2 f4_h(float4 v) {
    __half2 h01(__float2half_rn(v.x), __float2half_rn(v.y));
    __half2 h23(__float2half_rn(v.z), __float2half_rn(v.w));
    uint2 h;
    h.x = *(uint32_t*)&h01; h.y = *(uint32_t*)&h23;
    return h;
}

// ---------------- launch 0: degree atomics + W1 transpose (independent) ------
__global__ void k_deg_w1t(const int* __restrict__ dst, const float* __restrict__ w,
                          const float* __restrict__ W1) {
    int tid = threadIdx.x;
    if (blockIdx.x < 625) {
        int e = blockIdx.x * 256 + tid;
        if (e < NEDGES) {
            int d = dst[e];
            atomicAdd(&g_deg[d], w[e]);
            atomicAdd(&g_cnt[d], 1);
        }
    } else {
        __shared__ float s[32][33];
        int bidx = blockIdx.x - 625;
        int n0 = (bidx & 31) * 32;
        int k0 = (bidx >> 5) * 32;
        int tx = tid & 31, ty = tid >> 5;
        #pragma unroll
        for (int i = 0; i < 32; i += 8) {
            int k = k0 + ty + i, n = n0 + tx;
            if (k < FTEXT) s[ty + i][tx] = W1[(size_t)k * FHID + n];
        }
        __syncthreads();
        #pragma unroll
        for (int i = 0; i < 32; i += 8) {
            int n = n0 + ty + i, k = k0 + tx;
            if (k < FTEXT) g_W1t[(size_t)n * FTEXT + k] = s[tx][ty + i];
        }
    }
}

// ---------------- launch 1: warp-shuffle scan + dinv ----------------
__global__ void k_scandinv() {
    const int CH = 20;
    __shared__ int wtot[32];
    __shared__ int s_total;
    int t = threadIdx.x;
    int lane = t & 31, wid = t >> 5;
    int base = t * CH;
    int loc[CH];
    int sum = 0;
    #pragma unroll
    for (int i = 0; i < CH; i++) {
        int idx = base + i;
        int v = 0;
        if (idx < NNODES) {
            v = g_cnt[idx];
            float d = g_deg[idx];
            g_dinv[idx] = (d > 0.f) ? rsqrtf(d) : 0.f;
        }
        loc[i] = sum;
        sum += v;
    }
    int inc = sum;
    #pragma unroll
    for (int off = 1; off < 32; off <<= 1) {
        int v = __shfl_up_sync(0xffffffffu, inc, off);
        if (lane >= off) inc += v;
    }
    if (lane == 31) wtot[wid] = inc;
    __syncthreads();
    if (wid == 0) {
        int v = wtot[lane];
        int wi = v;
        #pragma unroll
        for (int off = 1; off < 32; off <<= 1) {
            int u = __shfl_up_sync(0xffffffffu, wi, off);
            if (lane >= off) wi += u;
        }
        wtot[lane] = wi - v;
        if (lane == 31) s_total = wi;
    }
    __syncthreads();
    int off0 = wtot[wid] + inc - sum;
    #pragma unroll
    for (int i = 0; i < CH; i++) {
        int idx = base + i;
        if (idx < NNODES) g_rowptr[idx] = off0 + loc[i];
    }
    if (t == 0) g_rowptr[NNODES] = s_total;
}

// ---------------- launch 2: fill CSR + T1 split-K (merged) ----------------
__global__ void __launch_bounds__(256) k_fill_t1(
    const int* __restrict__ src, const int* __restrict__ dst,
    const float* __restrict__ w,
    const float* __restrict__ img, const float* __restrict__ W2)
{
    __shared__ float As[16][64 + 1];
    __shared__ float Bs[16][64 + 1];
    int tid = threadIdx.x;
    if (blockIdx.x < 625) {
        int e = blockIdx.x * 256 + tid;
        if (e < NEDGES) {
            int s = src[e], d = dst[e];
            float nm = g_dinv[s] * w[e] * g_dinv[d];
            int pos = g_rowptr[d] + atomicAdd(&g_cursor[d], 1);
            g_colsrc[pos] = s;
            g_colw[pos]   = nm;
        }
    } else {
        int bidx = blockIdx.x - 625;          // 0..207
        int col0 = (bidx & 15) * 64;
        int sk = bidx >> 4;
        int kbase = sk * 128;
        const int BK = 16;
        int tx = tid & 15, ty = tid >> 4;
        float acc[4][4] = {};
        int r = tid >> 2, kq = (tid & 3) * 4;
        for (int t0 = 0; t0 < 128; t0 += BK) {
            float4 av = *(const float4*)(img + (size_t)r * FOUT + kbase + t0 + kq);
            As[kq + 0][r] = av.x; As[kq + 1][r] = av.y;
            As[kq + 2][r] = av.z; As[kq + 3][r] = av.w;
            float4 bv = *(const float4*)(W2 + (size_t)(col0 + r) * FOUT + kbase + t0 + kq);
            Bs[kq + 0][r] = bv.x; Bs[kq + 1][r] = bv.y;
            Bs[kq + 2][r] = bv.z; Bs[kq + 3][r] = bv.w;
            __syncthreads();
            #pragma unroll
            for (int k = 0; k < BK; k++) {
                float a[4], b[4];
                #pragma unroll
                for (int i = 0; i < 4; i++) a[i] = As[k][ty * 4 + i];
                #pragma unroll
                for (int j = 0; j < 4; j++) b[j] = Bs[k][tx * 4 + j];
                #pragma unroll
                for (int i = 0; i < 4; i++)
                    #pragma unroll
                    for (int j = 0; j < 4; j++)
                        acc[i][j] += a[i] * b[j];
            }
            __syncthreads();
        }
        float* cp = g_T1p + (size_t)sk * (BBATCH * FHID);
        #pragma unroll
        for (int i = 0; i < 4; i++) {
            int b = ty * 4 + i;
            #pragma unroll
            for (int j = 0; j < 4; j++)
                cp[(size_t)b * FHID + col0 + tx * 4 + j] = acc[i][j];
        }
    }
}

// ---------------- launch 3: Y = A @ X (width 300), float2 gather, unroll x2 --
__global__ void k_aggY(const float* __restrict__ X) {
    __shared__ int   ss[128];
    __shared__ float sw[128];
    int n = blockIdx.x;
    int tid = threadIdx.x;
    int st = g_rowptr[n], en = g_rowptr[n + 1];
    float2 a0 = make_float2(0.f, 0.f);     // cols 2t, 2t+1
    float2 a1 = make_float2(0.f, 0.f);     // cols 256+2t (t<22)
    bool hasT = (tid < 22);
    for (int e0 = st; e0 < en; e0 += 128) {
        int ne = min(128, en - e0);
        if (tid < ne) { ss[tid] = g_colsrc[e0 + tid]; sw[tid] = g_colw[e0 + tid]; }
        __syncthreads();
        int j = 0;
        for (; j + 2 <= ne; j += 2) {
            const float2* x0 = (const float2*)(X + (size_t)ss[j] * FTEXT);
            const float2* x1 = (const float2*)(X + (size_t)ss[j + 1] * FTEXT);
            float w0 = sw[j], w1 = sw[j + 1];
            float2 p0 = x0[tid], q0 = x1[tid];
            float2 p1 = make_float2(0.f, 0.f), q1 = make_float2(0.f, 0.f);
            if (hasT) { p1 = x0[128 + tid]; q1 = x1[128 + tid]; }
            a0.x += w0 * p0.x + w1 * q0.x;
            a0.y += w0 * p0.y + w1 * q0.y;
            a1.x += w0 * p1.x + w1 * q1.x;
            a1.y += w0 * p1.y + w1 * q1.y;
        }
        if (j < ne) {
            const float2* x0 = (const float2*)(X + (size_t)ss[j] * FTEXT);
            float w0 = sw[j];
            float2 p0 = x0[tid];
            a0.x += w0 * p0.x;
            a0.y += w0 * p0.y;
            if (hasT) {
                float2 p1 = x0[128 + tid];
                a1.x += w0 * p1.x;
                a1.y += w0 * p1.y;
            }
        }
        __syncthreads();
    }
    float2* yr = (float2*)(g_Y + (size_t)n * FTEXT);
    yr[tid] = a0;
    if (hasT) yr[128 + tid] = a1;
}

// ---------------- fp16x2 GEMM core, 128x64 CTA tile, 256 threads -------------
// C = A @ B^T via D = (ah+al)·bh : error ~ a·(b-bh) ~ 2^-12 relative.
template<bool BIAS, bool LEAKY>
__device__ __forceinline__ void gemm_core(
    const float* __restrict__ A, int lda,
    const float* __restrict__ B, int ldb,
    float* __restrict__ C, int ldc,
    const float* __restrict__ bias,
    int M, int N, int K, int bx, int by, char* smem)
{
    const int A_BYTES = 128 * 80;          // per A buffer (hi or lo)
    const int B_BYTES = 64 * 80;           // B hi only
    const int STAGE   = 2 * A_BYTES + B_BYTES;   // 25600

    int tid  = threadIdx.x;
    int wid  = tid >> 5, lane = tid & 31;
    int wm   = wid & 3, wn = wid >> 2;
    int row0 = by * 128;
    int col0 = bx * 64;
    uint32_t smem_u = smem_to_u32(smem);

    float acc[2][4][4];
    #pragma unroll
    for (int mt = 0; mt < 2; mt++)
        #pragma unroll
        for (int nt = 0; nt < 4; nt++)
            #pragma unroll
            for (int q = 0; q < 4; q++) acc[mt][nt][q] = 0.f;

    float4 aR[4], bR[2];
    const int nT = (K + 31) >> 5;

    auto LDG = [&](int t) {
        int kb = t * 32;
        #pragma unroll
        for (int i = 0; i < 4; i++) {
            int idx = tid + i * 256;
            int r = idx >> 3, kk = (idx & 7) * 4;
            int row = row0 + r, kg = kb + kk;
            float4 v = make_float4(0.f, 0.f, 0.f, 0.f);
            if (row < M && kg < K) v = *(const float4*)(A + (size_t)row * lda + kg);
            aR[i] = v;
        }
        #pragma unroll
        for (int i = 0; i < 2; i++) {
            int idx = tid + i * 256;
            int c = idx >> 3, kk = (idx & 7) * 4;
            int col = col0 + c, kg = kb + kk;
            float4 v = make_float4(0.f, 0.f, 0.f, 0.f);
            if (col < N && kg < K) v = *(const float4*)(B + (size_t)col * ldb + kg);
            bR[i] = v;
        }
    };
    auto STS = [&](int s) {
        char* base = smem + s * STAGE;
        #pragma unroll
        for (int i = 0; i < 4; i++) {
            int idx = tid + i * 256;
            int r = idx >> 3, kk = (idx & 7) * 4;
            uint2 h, l;
            f4_hilo_h(aR[i], h, l);
            *(uint2*)(base + r * 80 + kk * 2) = h;
            *(uint2*)(base + A_BYTES + r * 80 + kk * 2) = l;
        }
        #pragma unroll
        for (int i = 0; i < 2; i++) {
            int idx = tid + i * 256;
            int c = idx >> 3, kk = (idx & 7) * 4;
            *(uint2*)(base + 2 * A_BYTES + c * 80 + kk * 2) = f4_h(bR[i]);
        }
    };
    auto COMPUTE = [&](int s) {
        uint32_t sb = smem_u + s * STAGE;
        uint32_t aH = sb + (uint32_t)((wm * 32 + (lane & 15)) * 80 + (lane >> 4) * 16);
        uint32_t aL = aH + A_BYTES;
        uint32_t bH = sb + 2 * A_BYTES +
            (uint32_t)((wn * 32 + ((lane >> 4) & 1) * 8 + (lane & 7)) * 80 + ((lane >> 3) & 1) * 16);
        #pragma unroll
        for (int ks = 0; ks < 2; ks++) {
            uint32_t ah[2][4], al[2][4], bh[2][4];
            #pragma unroll
            for (int mt = 0; mt < 2; mt++) {
                ldsm_x4(ah[mt], aH + mt * 16 * 80 + ks * 32);
                ldsm_x4(al[mt], aL + mt * 16 * 80 + ks * 32);
            }
            #pragma unroll
            for (int g = 0; g < 2; g++)
                ldsm_x4(bh[g], bH + g * 16 * 80 + ks * 32);
            #pragma unroll
            for (int mt = 0; mt < 2; mt++)
                #pragma unroll
                for (int nt = 0; nt < 4; nt++) {
                    const uint32_t* ph = &bh[nt >> 1][(nt & 1) * 2];
                    mma_f16(acc[mt][nt], ah[mt], ph);
                    mma_f16(acc[mt][nt], al[mt], ph);
                }
        }
    };

    LDG(0);
    STS(0);
    if (nT > 1) LDG(1);
    __syncthreads();
    for (int t = 0; t < nT; t++) {
        COMPUTE(t & 1);
        if (t + 1 < nT) STS((t + 1) & 1);
        __syncthreads();
        if (t + 2 < nT) LDG(t + 2);
    }

    int rw = row0 + wm * 32;
    int cw = col0 + wn * 32;
    #pragma unroll
    for (int mt = 0; mt < 2; mt++) {
        #pragma unroll
        for (int half = 0; half < 2; half++) {
            int row = rw + mt * 16 + (lane >> 2) + half * 8;
            if (row >= M) continue;
            #pragma unroll
            for (int nt = 0; nt < 4; nt++) {
                int col = cw + nt * 8 + (lane & 3) * 2;
                if (col >= N) continue;
                float v0 = acc[mt][nt][half * 2 + 0];
                float v1 = acc[mt][nt][half * 2 + 1];
                if (BIAS) { v0 += bias[col]; v1 += bias[col + 1]; }
                if (LEAKY) {
                    v0 = (v0 >= 0.f) ? v0 : NEG_SLOPE * v0;
                    v1 = (v1 >= 0.f) ? v1 : NEG_SLOPE * v1;
                }
                float2 o; o.x = v0; o.y = v1;
                *(float2*)(C + (size_t)row * ldc + col) = o;
            }
        }
    }
}

// ---------------- launch 4: GEMM1 + T1 reduce + imgb2 (merged) ---------------
__global__ void __launch_bounds__(256, 2) k_gemm1_fused(
    const float* __restrict__ A, const float* __restrict__ B,
    float* __restrict__ C, const float* __restrict__ bias,
    const float* __restrict__ img, const float* __restrict__ b2)
{
    extern __shared__ char smem[];
    if (blockIdx.x < G1_GRID) {
        int bx = blockIdx.x & 15;
        int by = blockIdx.x >> 4;
        gemm_core<true, true>(A, FTEXT, B, FTEXT, C, FHID, bias,
                              NNODES, FHID, FTEXT, bx, by, smem);
    } else if (blockIdx.x < G1_GRID + 256) {
        int idx = (blockIdx.x - G1_GRID) * 256 + threadIdx.x;
        float acc = 0.f;
        #pragma unroll
        for (int s = 0; s < NSPLIT; s++)
            acc += g_T1p[(size_t)s * (BBATCH * FHID) + idx];
        g_T1[idx] = acc;
    } else {
        int wid = threadIdx.x >> 5, lane = threadIdx.x & 31;
        for (int i = 0; i < 8; i++) {
            int b = wid * 8 + i;
            float acc = 0.f;
            for (int k = lane; k < FOUT; k += 32)
                acc += img[(size_t)b * FOUT + k] * b2[k];
            #pragma unroll
            for (int off = 16; off > 0; off >>= 1)
                acc += __shfl_down_sync(0xffffffffu, acc, off);
            if (lane == 0) g_imgb2[b] = acc;
        }
    }
}

// ---------------- launch 5: T2 = X1 @ T1^T, 64-row tiles, fp16x2 -------------
__global__ void __launch_bounds__(128, 4) k_t2(
    const float* __restrict__ A, const float* __restrict__ B,
    float* __restrict__ C)
{
    extern __shared__ char smem[];
    const int A64 = 64 * 80;
    const int B64 = 64 * 80;
    const int STAGE = 2 * A64 + B64;       // 15360
    const int M = NNODES, K = FHID;

    int tid = threadIdx.x;
    int wid = tid >> 5, lane = tid & 31;
    int wm = wid & 1, wn = wid >> 1;
    int row0 = blockIdx.x * 64;
    uint32_t smem_u = smem_to_u32(smem);

    float acc[2][4][4];
    #pragma unroll
    for (int mt = 0; mt < 2; mt++)
        #pragma unroll
        for (int nt = 0; nt < 4; nt++)
            #pragma unroll
            for (int q = 0; q < 4; q++) acc[mt][nt][q] = 0.f;

    float4 aR[4], bR[4];
    const int nT = K >> 5;

    auto LDG = [&](int t) {
        int kb = t * 32;
        #pragma unroll
        for (int i = 0; i < 4; i++) {
            int idx = tid + i * 128;
            int r = idx >> 3, kk = (idx & 7) * 4;
            int row = row0 + r; row = (row < M) ? row : (M - 1);
            aR[i] = *(const float4*)(A + (size_t)row * K + kb + kk);
            bR[i] = *(const float4*)(B + (size_t)r * K + kb + kk);
        }
    };
    auto STS = [&](int s) {
        char* base = smem + s * STAGE;
        #pragma unroll
        for (int i = 0; i < 4; i++) {
            int idx = tid + i * 128;
            int r = idx >> 3, kk = (idx & 7) * 4;
            uint2 h, l;
            f4_hilo_h(aR[i], h, l);
            *(uint2*)(base + r * 80 + kk * 2) = h;
            *(uint2*)(base + A64 + r * 80 + kk * 2) = l;
            *(uint2*)(base + 2 * A64 + r * 80 + kk * 2) = f4_h(bR[i]);
        }
    };
    auto COMPUTE = [&](int s) {
        uint32_t sb = smem_u + s * STAGE;
        uint32_t aH = sb + (uint32_t)((wm * 32 + (lane & 15)) * 80 + (lane >> 4) * 16);
        uint32_t aL = aH + A64;
        uint32_t bH = sb + 2 * A64 +
            (uint32_t)((wn * 32 + ((lane >> 4) & 1) * 8 + (lane & 7)) * 80 + ((lane >> 3) & 1) * 16);
        #pragma unroll
        for (int ks = 0; ks < 2; ks++) {
            uint32_t ah[2][4], al[2][4], bh[2][4];
            #pragma unroll
            for (int mt = 0; mt < 2; mt++) {
                ldsm_x4(ah[mt], aH + mt * 16 * 80 + ks * 32);
                ldsm_x4(al[mt], aL + mt * 16 * 80 + ks * 32);
            }
            #pragma unroll
            for (int g = 0; g < 2; g++)
                ldsm_x4(bh[g], bH + g * 16 * 80 + ks * 32);
            #pragma unroll
            for (int mt = 0; mt < 2; mt++)
                #pragma unroll
                for (int nt = 0; nt < 4; nt++) {
                    const uint32_t* ph = &bh[nt >> 1][(nt & 1) * 2];
                    mma_f16(acc[mt][nt], ah[mt], ph);
                    mma_f16(acc[mt][nt], al[mt], ph);
                }
        }
    };

    LDG(0);
    STS(0);
    LDG(1);
    __syncthreads();
    for (int t = 0; t < nT; t++) {
        COMPUTE(t & 1);
        if (t + 1 < nT) STS((t + 1) & 1);
        __syncthreads();
        if (t + 2 < nT) LDG(t + 2);
    }

    int rw = row0 + wm * 32;
    int cw = wn * 32;
    #pragma unroll
    for (int mt = 0; mt < 2; mt++) {
        #pragma unroll
        for (int half = 0; half < 2; half++) {
            int row = rw + mt * 16 + (lane >> 2) + half * 8;
            if (row >= M) continue;
            #pragma unroll
            for (int nt = 0; nt < 4; nt++) {
                int col = cw + nt * 8 + (lane & 3) * 2;
                float2 o;
                o.x = acc[mt][nt][half * 2 + 0];
                o.y = acc[mt][nt][half * 2 + 1];
                *(float2*)(C + (size_t)row * BBATCH + col) = o;
            }
        }
    }
}

// ---------------- launch 6: output agg + transpose + re-zero scratch ---------
__global__ void __launch_bounds__(256) k_aggOutT(float* __restrict__ out) {
    if (blockIdx.x >= 625) {
        int i = (blockIdx.x - 625) * 256 + threadIdx.x;
        if (i < NNODES) { g_deg[i] = 0.f; g_cnt[i] = 0; g_cursor[i] = 0; }
        return;
    }
    __shared__ float s[32][65];
    int n0 = blockIdx.x * 32;
    int tid = threadIdx.x;
    int slot = tid >> 6;
    int b = tid & 63;
    float bias = g_imgb2[b];
    for (int rnd = 0; rnd < 8; rnd++) {
        int nl = rnd * 4 + slot;
        int n = n0 + nl;
        float acc = bias;
        int st = g_rowptr[n], en = g_rowptr[n + 1];
        for (int e = st; e < en; e++)
            acc += g_colw[e] * g_T2[(size_t)g_colsrc[e] * BBATCH + b];
        s[nl][b] = acc;
    }
    __syncthreads();
    #pragma unroll
    for (int i = 0; i < 8; i++) {
        int idx = tid + i * 256;
        int bb = idx >> 5, nn = idx & 31;
        out[(size_t)bb * NNODES + n0 + nn] = s[nn][bb];
    }
}

// ---------------- launch ----------------
extern "C" void kernel_launch(void* const* d_in, const int* in_sizes, int n_in,
                              void* d_out, int out_size) {
    const float* img  = (const float*)d_in[0];
    const float* nf   = (const float*)d_in[1];
    const int*   esrc = (const int*)d_in[2];
    const int*   edst = (const int*)d_in[3];
    const float* ew   = (const float*)d_in[4];
    const float* W1   = (const float*)d_in[5];
    const float* b1   = (const float*)d_in[6];
    const float* W2   = (const float*)d_in[7];
    const float* b2   = (const float*)d_in[8];
    float* out = (float*)d_out;

    float *dY, *dX1, *dW1t, *dT1, *dT2;
    cudaGetSymbolAddress((void**)&dY,   g_Y);
    cudaGetSymbolAddress((void**)&dX1,  g_X1);
    cudaGetSymbolAddress((void**)&dW1t, g_W1t);
    cudaGetSymbolAddress((void**)&dT1,  g_T1);
    cudaGetSymbolAddress((void**)&dT2,  g_T2);

    const int SMEM1 = 51200;   // gemm_core: 2 stages x 25600
    const int SMEM2 = 30720;   // k_t2:      2 stages x 15360
    cudaFuncSetAttribute(k_gemm1_fused, cudaFuncAttributeMaxDynamicSharedMemorySize, SMEM1);
    cudaFuncSetAttribute(k_t2,          cudaFuncAttributeMaxDynamicSharedMemorySize, SMEM2);

    // 0: degree atomics + W1 transpose
    k_deg_w1t<<<625 + 320, 256>>>(edst, ew, W1);
    // 1: scan + dinv
    k_scandinv<<<1, 1024>>>();
    // 2: CSR fill + T1 split-K
    k_fill_t1<<<625 + 16 * NSPLIT, 256>>>(esrc, edst, ew, img, W2);
    // 3: layer-1 aggregation (float2 gather)
    k_aggY<<<NNODES, 128>>>(nf);
    // 4: GEMM1 + T1 reduce + imgb2 (fp16x2)
    k_gemm1_fused<<<G1_GRID + 256 + 1, 256, SMEM1>>>(dY, dW1t, dX1, b1, img, b2);
    // 5: T2 (fp16x2, 64-row tiles)
    k_t2<<<(NNODES + 63) / 64, 128, SMEM2>>>(dX1, dT1, dT2);
    // 6: output aggregation + transpose + re-zero scratch
    k_aggOutT<<<625 + 79, 256>>>(out);
}